// round 13
// baseline (speedup 1.0000x reference)
#include <cuda_runtime.h>
#include <cuda_bf16.h>
#include <math.h>
#include <stdint.h>

// Model dims
#define BBATCH 4
#define TSEQ   512
#define BT     2048
#define DMODEL 1024
#define NHEAD  16
#define HDIM   64
#define FINNER 4096
#define VOCAB  32000
#define NLAYER 8

typedef __nv_bfloat16 bf16;

// ---------------- scratch ----------------
__device__ float g_h   [BT * DMODEL];
__device__ float g_x   [BT * DMODEL];
__device__ float g_o   [BT * DMODEL];
__device__ float g_part[2 * BT * DMODEL];
__device__ float g_ff  [BT * FINNER];
__device__ float g_qkv [BT * 3 * DMODEL];
__device__ float g_vt  [(size_t)BBATCH * NHEAD * HDIM * TSEQ];
__device__ float g_sc  [(size_t)BBATCH * NHEAD * TSEQ * TSEQ];
__device__ float g_enc [4 * BT * DMODEL];
__device__ float g_wot [NLAYER * DMODEL * DMODEL];
__device__ float g_bos [NLAYER * DMODEL];
__device__ float g_wqkv[(size_t)NLAYER * 3 * DMODEL * DMODEL];
__device__ float g_bqkv[NLAYER * 3 * DMODEL];
__device__ float g_w1c [(size_t)NLAYER * FINNER * DMODEL];
__device__ float g_w2c [(size_t)NLAYER * DMODEL * FINNER];
__device__ float g_skwc[(size_t)NLAYER * DMODEL * 2 * DMODEL];
__device__ float g_wtec[(size_t)VOCAB * DMODEL];

// ---------------- helpers ----------------
__device__ __forceinline__ unsigned f2tf(float x) {
    unsigned r; asm("cvt.rna.tf32.f32 %0, %1;" : "=r"(r) : "f"(x)); return r;
}
__device__ __forceinline__ float tfr(float x) { return __uint_as_float(f2tf(x)); }
__device__ __forceinline__ uint32_t s2u(const void* p) {
    uint32_t a;
    asm("{ .reg .u64 t; cvta.to.shared.u64 t, %1; cvt.u32.u64 %0, t; }" : "=r"(a) : "l"(p));
    return a;
}
#define CP_ASYNC16(dst, src) \
    asm volatile("cp.async.cg.shared.global [%0], [%1], 16;" :: "r"(dst), "l"(src))
#define CP_COMMIT() asm volatile("cp.async.commit_group;")
#define CP_WAIT0()  asm volatile("cp.async.wait_group 0;")
#define CP_WAIT1()  asm volatile("cp.async.wait_group 1;")

__device__ __forceinline__ void mma_tf32(float c[4], unsigned a0, unsigned a1,
                                         unsigned a2, unsigned a3,
                                         unsigned b0, unsigned b1) {
    asm volatile(
        "mma.sync.aligned.m16n8k8.row.col.f32.tf32.tf32.f32 "
        "{%0,%1,%2,%3}, {%4,%5,%6,%7}, {%8,%9}, {%0,%1,%2,%3};"
        : "+f"(c[0]), "+f"(c[1]), "+f"(c[2]), "+f"(c[3])
        : "r"(a0), "r"(a1), "r"(a2), "r"(a3), "r"(b0), "r"(b1));
}
__device__ __forceinline__ void mma_bf16x(float c[4], unsigned a0, unsigned a1,
                                          unsigned a2, unsigned a3,
                                          unsigned b0, unsigned b1) {
    asm volatile(
        "mma.sync.aligned.m16n8k16.row.col.f32.bf16.bf16.f32 "
        "{%0,%1,%2,%3}, {%4,%5,%6,%7}, {%8,%9}, {%0,%1,%2,%3};"
        : "+f"(c[0]), "+f"(c[1]), "+f"(c[2]), "+f"(c[3])
        : "r"(a0), "r"(a1), "r"(a2), "r"(a3), "r"(b0), "r"(b1));
}
__device__ __forceinline__ void split8(float4 v0, float4 v1, uint4& hi, uint4& lo) {
    float f[8] = {v0.x, v0.y, v0.z, v0.w, v1.x, v1.y, v1.z, v1.w};
    uint32_t hs[8], ls[8];
    #pragma unroll
    for (int i = 0; i < 8; i++) {
        bf16 h = __float2bfloat16(f[i]);
        bf16 l = __float2bfloat16(f[i] - __bfloat162float(h));
        hs[i] = *(unsigned short*)&h;
        ls[i] = *(unsigned short*)&l;
    }
    hi = make_uint4(hs[0] | (hs[1] << 16), hs[2] | (hs[3] << 16),
                    hs[4] | (hs[5] << 16), hs[6] | (hs[7] << 16));
    lo = make_uint4(ls[0] | (ls[1] << 16), ls[2] | (ls[3] << 16),
                    ls[4] | (ls[5] << 16), ls[6] | (ls[7] << 16));
}

// ---------------- prep kernels ----------------
__global__ void tf32_copy(const float* __restrict__ in, float* __restrict__ out, long n) {
    long i = ((long)blockIdx.x * 256 + threadIdx.x) * 4;
    if (i >= n) return;
    float4 v = *(const float4*)(in + i);
    v.x = tfr(v.x); v.y = tfr(v.y); v.z = tfr(v.z); v.w = tfr(v.w);
    *(float4*)(out + i) = v;
}

__global__ void prep_wqkvb(const float* __restrict__ Wq, const float* __restrict__ Wk,
                           const float* __restrict__ Wv,
                           const float* __restrict__ bq, const float* __restrict__ bk,
                           const float* __restrict__ bv,
                           float* __restrict__ W, float* __restrict__ bias) {
    long idx = (long)blockIdx.x * 256 + threadIdx.x;
    if (idx >= (long)NLAYER * 3 * DMODEL * DMODEL) return;
    int l = (int)(idx / (3L * DMODEL * DMODEL));
    long rem = idx - (long)l * 3 * DMODEL * DMODEL;
    int r = (int)(rem >> 10), d = (int)(rem & 1023);
    int sel = r >> 10, rn = r & 1023;
    const float* src = sel == 0 ? Wq : (sel == 1 ? Wk : Wv);
    W[idx] = tfr(src[((long)l * DMODEL + rn) * DMODEL + d]);
    if (idx < NLAYER * 3 * DMODEL) {
        int lb = (int)(idx / (3 * DMODEL)), rb = (int)(idx % (3 * DMODEL));
        int selb = rb >> 10, rnb = rb & 1023;
        const float* b = selb == 0 ? bq : (selb == 1 ? bk : bv);
        bias[idx] = b[lb * DMODEL + rnb];
    }
}

__global__ void prep_wot(const float* __restrict__ Wo, const float* __restrict__ gate,
                         float* __restrict__ wot) {
    long idx = (long)blockIdx.x * 256 + threadIdx.x;
    if (idx >= (long)NLAYER * DMODEL * DMODEL) return;
    int l = (int)(idx >> 20);
    int d = (int)((idx >> 10) & 1023);
    int c = (int)(idx & 1023);
    int n = c >> 6, hh = c & 63;
    wot[idx] = tfr(Wo[((long)(l * NHEAD + n)) * (DMODEL * HDIM) + (long)d * HDIM + hh]
                   * gate[l * NHEAD + n]);
}

__global__ void prep_bos(const float* __restrict__ bo, const float* __restrict__ gate,
                         float* __restrict__ bos) {
    int idx = blockIdx.x * 256 + threadIdx.x;
    if (idx >= NLAYER * DMODEL) return;
    int l = idx >> 10, d = idx & 1023;
    float s = 0.f;
    for (int n = 0; n < NHEAD; n++)
        s += gate[l * NHEAD + n] * bo[(long)(l * NHEAD + n) * DMODEL + d];
    bos[idx] = s;
}

__global__ void embed_k(const int* __restrict__ ids, const float* __restrict__ wte,
                        const float* __restrict__ wpe, float* __restrict__ h) {
    long idx = (long)blockIdx.x * 256 + threadIdx.x;
    if (idx >= (long)BT * DMODEL) return;
    int bt = (int)(idx >> 10), d = (int)(idx & 1023);
    int t = bt & (TSEQ - 1);
    h[idx] = wte[(long)ids[bt] * DMODEL + d] + wpe[(long)t * DMODEL + d];
}

// ---------------- layernorm (layer-0 entry only) ----------------
__global__ void layernorm_k(const float* __restrict__ in, float* __restrict__ out,
                            const float* __restrict__ g, const float* __restrict__ b) {
    int row = blockIdx.x;
    const float* x = in + (long)row * DMODEL;
    float* y = out + (long)row * DMODEL;
    __shared__ float red[256];
    int tid = threadIdx.x;
    float s = 0.f;
    for (int i = tid; i < DMODEL; i += 256) s += x[i];
    red[tid] = s; __syncthreads();
    for (int o = 128; o > 0; o >>= 1) { if (tid < o) red[tid] += red[tid + o]; __syncthreads(); }
    float mean = red[0] * (1.0f / DMODEL);
    __syncthreads();
    float v = 0.f;
    for (int i = tid; i < DMODEL; i += 256) { float d = x[i] - mean; v += d * d; }
    red[tid] = v; __syncthreads();
    for (int o = 128; o > 0; o >>= 1) { if (tid < o) red[tid] += red[tid + o]; __syncthreads(); }
    float inv = rsqrtf(red[0] * (1.0f / DMODEL) + 1e-5f);
    for (int i = tid; i < DMODEL; i += 256)
        y[i] = tfr((x[i] - mean) * inv * g[i] + b[i]);
}

// ---------------- fused: h = (ADDH? h : 0) + p0 + p1 + bias;  x = LN(h) ------
template<bool ADDH>
__global__ void add_ln(const float* __restrict__ part, const float* __restrict__ bias,
                       float* __restrict__ h, float* __restrict__ x,
                       const float* __restrict__ g, const float* __restrict__ b) {
    int row = blockIdx.x;
    int tid = threadIdx.x;
    __shared__ float buf[DMODEL];
    __shared__ float red[256];
    const float* p0 = part + (long)row * DMODEL;
    const float* p1 = part + (long)BT * DMODEL + (long)row * DMODEL;
    float* hp = h + (long)row * DMODEL;
    float* xp = x + (long)row * DMODEL;
    float s = 0.f;
    for (int i = tid; i < DMODEL; i += 256) {
        float v = p0[i] + p1[i] + bias[i];
        if (ADDH) v += hp[i];
        buf[i] = v;
        hp[i] = v;
        s += v;
    }
    red[tid] = s; __syncthreads();
    for (int o = 128; o > 0; o >>= 1) { if (tid < o) red[tid] += red[tid + o]; __syncthreads(); }
    float mean = red[0] * (1.0f / DMODEL);
    __syncthreads();
    float v2 = 0.f;
    for (int i = tid; i < DMODEL; i += 256) { float d = buf[i] - mean; v2 += d * d; }
    red[tid] = v2; __syncthreads();
    for (int o = 128; o > 0; o >>= 1) { if (tid < o) red[tid] += red[tid + o]; __syncthreads(); }
    float inv = rsqrtf(red[0] * (1.0f / DMODEL) + 1e-5f);
    for (int i = tid; i < DMODEL; i += 256)
        xp[i] = tfr((buf[i] - mean) * inv * g[i] + b[i]);
}

__global__ void add2_k(const float* __restrict__ part, const float* __restrict__ bias,
                       float* __restrict__ out) {
    long i = ((long)blockIdx.x * 256 + threadIdx.x) * 4;
    if (i >= (long)BT * DMODEL) return;
    int n = (int)(i & (DMODEL - 1));
    float4 p0 = *(const float4*)(part + i);
    float4 p1 = *(const float4*)(part + (long)BT * DMODEL + i);
    float4 b4 = *(const float4*)(bias + n);
    float4 r4 = *(const float4*)(out + i);
    float4 v;
    v.x = p0.x + p1.x + b4.x + r4.x;
    v.y = p0.y + p1.y + b4.y + r4.y;
    v.z = p0.z + p1.z + b4.z + r4.z;
    v.w = p0.w + p1.w + b4.w + r4.w;
    *(float4*)(out + i) = v;
}

// ---------------- tf32 GEMM, 2-stage cp.async, LDS.64 fragments ----------------
// Logical-k permutation: mma logical slot t <- physical 2t, t+4 <- physical 2t+1.
// Same mapping on A and B => identical products, pairs adjacent => LDS.64.
// Stride 40 floats: half-warp 64-bit frag loads cover all 32 banks once.
#define SMEM_STRIDE 40
#define TILE_U (128 * SMEM_STRIDE)
#define GEMM_SMEM_BYTES (4 * TILE_U * 4)   // 2 stages x (A+B) = 163840/2CTA fits

template<int EPI, bool BIAS, bool RES, bool CVTA, bool ROUND>
__global__ __launch_bounds__(256, 2) void gemm_cp(
    const float* __restrict__ A, const float* __restrict__ Bm,
    const float* __restrict__ bias, const float* __restrict__ res,
    float* __restrict__ C, int M, int N, int K, int lda, int ldb, int ldc) {
    extern __shared__ float sm[];
    float* As = sm;
    float* Bs = sm + 2 * TILE_U;
    const uint32_t AsU = s2u(As), BsU = s2u(Bs);

    int tid = threadIdx.x, lane = tid & 31, warp = tid >> 5;
    int wm = warp & 3, wn = warp >> 2;
    int m0 = blockIdx.y * 128, n0 = blockIdx.x * 128;
    const float* Ag = A + (long)m0 * lda;
    const float* Bg = Bm + (long)n0 * ldb;

    const float* Asrc[4]; const float* Bsrc[4];
    uint32_t Adst[4], Bdst[4];
    #pragma unroll
    for (int i = 0; i < 4; i++) {
        int idx = tid + i * 256;
        int r = idx >> 3, c = (idx & 7) * 4;
        Asrc[i] = Ag + (long)r * lda + c;
        Bsrc[i] = Bg + (long)r * ldb + c;
        Adst[i] = AsU + (uint32_t)(r * SMEM_STRIDE + c) * 4;
        Bdst[i] = BsU + (uint32_t)(r * SMEM_STRIDE + c) * 4;
    }

    float acc[2][8][4];
    #pragma unroll
    for (int i = 0; i < 2; i++)
        #pragma unroll
        for (int j = 0; j < 8; j++)
            #pragma unroll
            for (int q = 0; q < 4; q++) acc[i][j][q] = 0.f;

    int mrow = wm * 32 + (lane >> 2);
    int nrow = wn * 64 + (lane >> 2);
    int kt2 = (lane & 3) * 2;

    #pragma unroll
    for (int i = 0; i < 4; i++) {
        CP_ASYNC16(Adst[i], Asrc[i]);
        CP_ASYNC16(Bdst[i], Bsrc[i]);
    }
    CP_COMMIT();

    int p = 0;
    for (int k0 = 0; k0 < K; k0 += 32) {
        if (k0 + 32 < K) {
            uint32_t po = (uint32_t)((p ^ 1) * TILE_U) * 4;
            #pragma unroll
            for (int i = 0; i < 4; i++) {
                CP_ASYNC16(Adst[i] + po, Asrc[i] + k0 + 32);
                CP_ASYNC16(Bdst[i] + po, Bsrc[i] + k0 + 32);
            }
            CP_COMMIT();
            CP_WAIT1();
        } else {
            CP_WAIT0();
        }
        __syncthreads();
        const unsigned* Ab = (const unsigned*)(As + p * TILE_U);
        const unsigned* Bb = (const unsigned*)(Bs + p * TILE_U);
        #pragma unroll
        for (int ks = 0; ks < 4; ks++) {
            int kk2 = ks * 8 + kt2;
            uint2 afr[2][2];
            #pragma unroll
            for (int i = 0; i < 2; i++) {
                const unsigned* base = Ab + (mrow + i * 16) * SMEM_STRIDE;
                afr[i][0] = *(const uint2*)(base + kk2);
                afr[i][1] = *(const uint2*)(base + 8 * SMEM_STRIDE + kk2);
                if (CVTA) {
                    afr[i][0].x = f2tf(__uint_as_float(afr[i][0].x));
                    afr[i][0].y = f2tf(__uint_as_float(afr[i][0].y));
                    afr[i][1].x = f2tf(__uint_as_float(afr[i][1].x));
                    afr[i][1].y = f2tf(__uint_as_float(afr[i][1].y));
                }
            }
            #pragma unroll
            for (int j = 0; j < 8; j++) {
                const unsigned* bb = Bb + (nrow + j * 8) * SMEM_STRIDE;
                uint2 bv = *(const uint2*)(bb + kk2);
                #pragma unroll
                for (int i = 0; i < 2; i++)
                    mma_tf32(acc[i][j], afr[i][0].x, afr[i][1].x,
                             afr[i][0].y, afr[i][1].y, bv.x, bv.y);
            }
        }
        __syncthreads();
        p ^= 1;
    }

    #pragma unroll
    for (int i = 0; i < 2; i++) {
        int m = m0 + wm * 32 + i * 16 + (lane >> 2);
        #pragma unroll
        for (int j = 0; j < 8; j++) {
            int n = n0 + wn * 64 + j * 8 + (lane & 3) * 2;
            #pragma unroll
            for (int q = 0; q < 2; q++) {
                int mm = m + q * 8;
                float v0 = acc[i][j][q * 2 + 0];
                float v1 = acc[i][j][q * 2 + 1];
                if (BIAS) { v0 += bias[n]; v1 += bias[n + 1]; }
                if (RES)  { v0 += res[(long)mm * ldc + n]; v1 += res[(long)mm * ldc + n + 1]; }
                if (EPI == 2) {
                    v0 = 0.5f * v0 * (1.0f + erff(v0 * 0.70710678118654752f));
                    v1 = 0.5f * v1 * (1.0f + erff(v1 * 0.70710678118654752f));
                }
                if (ROUND) { v0 = tfr(v0); v1 = tfr(v1); }
                C[(long)mm * ldc + n]     = v0;
                C[(long)mm * ldc + n + 1] = v1;
            }
        }
    }
}

// ---------------- split-K / dual-source tf32 GEMM (same frag scheme) --------
template<bool CVTA>
__global__ __launch_bounds__(256, 2) void gemm_sk(
    const float* __restrict__ A0, const float* __restrict__ A1,
    const float* __restrict__ Bm, float* __restrict__ part,
    int K2, int lda, int ldb, int boff) {
    extern __shared__ float sm[];
    float* As = sm;
    float* Bs = sm + 2 * TILE_U;
    const uint32_t AsU = s2u(As), BsU = s2u(Bs);

    int tid = threadIdx.x, lane = tid & 31, warp = tid >> 5;
    int wm = warp & 3, wn = warp >> 2;
    int m0 = blockIdx.y * 128, n0 = blockIdx.x * 128;
    int z = blockIdx.z;
    const float* Ag = (z ? A1 : A0) + (long)m0 * lda;
    const float* Bg = Bm + (long)n0 * ldb + (long)z * boff;
    float* C = part + (long)z * BT * DMODEL;

    const float* Asrc[4]; const float* Bsrc[4];
    uint32_t Adst[4], Bdst[4];
    #pragma unroll
    for (int i = 0; i < 4; i++) {
        int idx = tid + i * 256;
        int r = idx >> 3, c = (idx & 7) * 4;
        Asrc[i] = Ag + (long)r * lda + c;
        Bsrc[i] = Bg + (long)r * ldb + c;
        Adst[i] = AsU + (uint32_t)(r * SMEM_STRIDE + c) * 4;
        Bdst[i] = BsU + (uint32_t)(r * SMEM_STRIDE + c) * 4;
    }

    float acc[2][8][4];
    #pragma unroll
    for (int i = 0; i < 2; i++)
        #pragma unroll
        for (int j = 0; j < 8; j++)
            #pragma unroll
            for (int q = 0; q < 4; q++) acc[i][j][q] = 0.f;

    int mrow = wm * 32 + (lane >> 2);
    int nrow = wn * 64 + (lane >> 2);
    int kt2 = (lane & 3) * 2;

    #pragma unroll
    for (int i = 0; i < 4; i++) {
        CP_ASYNC16(Adst[i], Asrc[i]);
        CP_ASYNC16(Bdst[i], Bsrc[i]);
    }
    CP_COMMIT();

    int p = 0;
    for (int k0 = 0; k0 < K2; k0 += 32) {
        if (k0 + 32 < K2) {
            uint32_t po = (uint32_t)((p ^ 1) * TILE_U) * 4;
            #pragma unroll
            for (int i = 0; i < 4; i++) {
                CP_ASYNC16(Adst[i] + po, Asrc[i] + k0 + 32);
                CP_ASYNC16(Bdst[i] + po, Bsrc[i] + k0 + 32);
            }
            CP_COMMIT();
            CP_WAIT1();
        } else {
            CP_WAIT0();
        }
        __syncthreads();
        const unsigned* Ab = (const unsigned*)(As + p * TILE_U);
        const unsigned* Bb = (const unsigned*)(Bs + p * TILE_U);
        #pragma unroll
        for (int ks = 0; ks < 4; ks++) {
            int kk2 = ks * 8 + kt2;
            uint2 afr[2][2];
            #pragma unroll
            for (int i = 0; i < 2; i++) {
                const unsigned* base = Ab + (mrow + i * 16) * SMEM_STRIDE;
                afr[i][0] = *(const uint2*)(base + kk2);
                afr[i][1] = *(const uint2*)(base + 8 * SMEM_STRIDE + kk2);
                if (CVTA) {
                    afr[i][0].x = f2tf(__uint_as_float(afr[i][0].x));
                    afr[i][0].y = f2tf(__uint_as_float(afr[i][0].y));
                    afr[i][1].x = f2tf(__uint_as_float(afr[i][1].x));
                    afr[i][1].y = f2tf(__uint_as_float(afr[i][1].y));
                }
            }
            #pragma unroll
            for (int j = 0; j < 8; j++) {
                const unsigned* bb = Bb + (nrow + j * 8) * SMEM_STRIDE;
                uint2 bv = *(const uint2*)(bb + kk2);
                #pragma unroll
                for (int i = 0; i < 2; i++)
                    mma_tf32(acc[i][j], afr[i][0].x, afr[i][1].x,
                             afr[i][0].y, afr[i][1].y, bv.x, bv.y);
            }
        }
        __syncthreads();
        p ^= 1;
    }

    #pragma unroll
    for (int i = 0; i < 2; i++) {
        int m = m0 + wm * 32 + i * 16 + (lane >> 2);
        #pragma unroll
        for (int j = 0; j < 8; j++) {
            int n = n0 + wn * 64 + j * 8 + (lane & 3) * 2;
            #pragma unroll
            for (int q = 0; q < 2; q++) {
                int mm = m + q * 8;
                C[(long)mm * DMODEL + n]     = acc[i][j][q * 2 + 0];
                C[(long)mm * DMODEL + n + 1] = acc[i][j][q * 2 + 1];
            }
        }
    }
}

// ---------------- attention scores: bf16 3-pass mma ----------------
#define SC_STR 36
#define SC_PLANE (128 * SC_STR)
#define SC_SMEM (4 * SC_PLANE * 4)

__global__ __launch_bounds__(256) void attn_scores_tc(
    const float* __restrict__ qkv, float* __restrict__ S) {
    int bh = blockIdx.z;
    int b = bh >> 4, n = bh & 15;
    int s0 = blockIdx.x * 128, t0 = blockIdx.y * 128;
    if (s0 > t0) return;
    extern __shared__ uint32_t smq[];
    uint32_t* Qh = smq;
    uint32_t* Ql = smq + SC_PLANE;
    uint32_t* Kh = smq + 2 * SC_PLANE;
    uint32_t* Kl = smq + 3 * SC_PLANE;
    int tid = threadIdx.x, lane = tid & 31, warp = tid >> 5;
    const float* Qp = qkv + ((long)(b * TSEQ + t0)) * (3 * DMODEL) + n * HDIM;
    const float* Kp = qkv + ((long)(b * TSEQ + s0)) * (3 * DMODEL) + DMODEL + n * HDIM;
    for (int g = tid; g < 2048; g += 256) {
        int isK = g >= 1024;
        int gg = g & 1023;
        int r = gg >> 3, c8 = (gg & 7) * 8;
        const float* src = (isK ? Kp : Qp) + (long)r * (3 * DMODEL) + c8;
        float4 v0 = *(const float4*)src;
        float4 v1 = *(const float4*)(src + 4);
        uint4 hi, lo;
        split8(v0, v1, hi, lo);
        int off = r * SC_STR + c8 / 2;
        *(uint4*)((isK ? Kh : Qh) + off) = hi;
        *(uint4*)((isK ? Kl : Ql) + off) = lo;
    }
    __syncthreads();

    int wm = warp & 3, wn = warp >> 2;
    int mrow = wm * 32 + (lane >> 2);
    int nrow = wn * 64 + (lane >> 2);
    int kt = lane & 3;
    float acc[2][8][4];
    #pragma unroll
    for (int i = 0; i < 2; i++)
        #pragma unroll
        for (int j = 0; j < 8; j++)
            #pragma unroll
            for (int q = 0; q < 4; q++) acc[i][j][q] = 0.f;

    const uint32_t* Ap[3] = {Qh, Qh, Ql};
    const uint32_t* Bp[3] = {Kh, Kl, Kh};
    #pragma unroll
    for (int p = 0; p < 3; p++) {
        #pragma unroll
        for (int ks = 0; ks < 4; ks++) {
            int kk = ks * 8 + kt;
            unsigned af[2][4];
            #pragma unroll
            for (int i = 0; i < 2; i++) {
                const uint32_t* base = Ap[p] + (mrow + i * 16) * SC_STR;
                af[i][0] = base[kk];
                af[i][1] = base[8 * SC_STR + kk];
                af[i][2] = base[kk + 4];
                af[i][3] = base[8 * SC_STR + kk + 4];
            }
            #pragma unroll
            for (int j = 0; j < 8; j++) {
                const uint32_t* bb = Bp[p] + (nrow + j * 8) * SC_STR;
                unsigned b0 = bb[kk], b1 = bb[kk + 4];
                #pragma unroll
                for (int i = 0; i < 2; i++)
                    mma_bf16x(acc[i][j], af[i][0], af[i][1], af[i][2], af[i][3], b0, b1);
            }
        }
    }
    float* Sp = S + ((long)bh * TSEQ + t0) * TSEQ + s0;
    #pragma unroll
    for (int i = 0; i < 2; i++) {
        int rr = wm * 32 + i * 16 + (lane >> 2);
        #pragma unroll
        for (int j = 0; j < 8; j++) {
            int cc = wn * 64 + j * 8 + (lane & 3) * 2;
            #pragma unroll
            for (int q = 0; q < 2; q++) {
                Sp[(long)(rr + q * 8) * TSEQ + cc]     = acc[i][j][q * 2 + 0] * 0.125f;
                Sp[(long)(rr + q * 8) * TSEQ + cc + 1] = acc[i][j][q * 2 + 1] * 0.125f;
            }
        }
    }
}

// ---------------- softmax ----------------
__global__ void softmax_rows(float* __restrict__ S) {
    int t = blockIdx.x, bh = blockIdx.y;
    float* row = S + ((long)bh * TSEQ + t) * TSEQ;
    int len = t + 1;
    __shared__ float red[128];
    int tid = threadIdx.x;
    float mx = -1e30f;
    for (int s = tid; s < len; s += 128) mx = fmaxf(mx, row[s]);
    red[tid] = mx; __syncthreads();
    for (int o = 64; o > 0; o >>= 1) { if (tid < o) red[tid] = fmaxf(red[tid], red[tid + o]); __syncthreads(); }
    mx = red[0]; __syncthreads();
    float sum = 0.f;
    for (int s = tid; s < len; s += 128) { float e = __expf(row[s] - mx); row[s] = e; sum += e; }
    red[tid] = sum; __syncthreads();
    for (int o = 64; o > 0; o >>= 1) { if (tid < o) red[tid] += red[tid + o]; __syncthreads(); }
    float inv = 1.0f / red[0];
    for (int s = tid; s < len; s += 128) row[s] *= inv;
    for (int s = len + tid; s < TSEQ; s += 128) row[s] = 0.0f;
}

// ---------------- V transpose ----------------
__global__ void transpose_v(const float* __restrict__ qkv, float* __restrict__ Vt) {
    int bh = blockIdx.z;
    int b = bh >> 4, n = bh & 15;
    int tt = blockIdx.x * 32, dd = blockIdx.y * 32;
    __shared__ float tile[32][33];
    int tx = threadIdx.x, ty = threadIdx.y;
    #pragma unroll
    for (int i = 0; i < 4; i++) {
        int t = tt + ty + i * 8;
        tile[ty + i * 8][tx] =
            qkv[((long)(b * TSEQ + t)) * (3 * DMODEL) + 2 * DMODEL + n * HDIM + dd + tx];
    }
    __syncthreads();
    #pragma unroll
    for (int i = 0; i < 4; i++) {
        int d = dd + ty + i * 8;
        Vt[((long)bh * HDIM + d) * TSEQ + tt + tx] = tile[tx][ty + i * 8];
    }
}

// ---------------- attention PV: bf16 3-pass mma (tf32-rounded output) -------
#define PV_STR 20

__global__ __launch_bounds__(256) void attn_pv_tc(
    const float* __restrict__ P, const float* __restrict__ Vt, float* __restrict__ O) {
    int bh = blockIdx.y;
    int b = bh >> 4, n = bh & 15;
    int t0 = blockIdx.x * 128;
    __shared__ uint32_t Ph[128 * PV_STR], Pl[128 * PV_STR];
    __shared__ uint32_t Vh[64 * PV_STR],  Vl[64 * PV_STR];
    int tid = threadIdx.x, lane = tid & 31, warp = tid >> 5;
    int wm = warp & 3, wn = warp >> 2;
    int mrow = wm * 32 + (lane >> 2);
    int nrow = wn * 32 + (lane >> 2);
    int kt = lane & 3;
    const float* Pp = P + ((long)bh * TSEQ + t0) * TSEQ;
    const float* Vp = Vt + (long)bh * HDIM * TSEQ;

    float acc[2][4][4];
    #pragma unroll
    for (int i = 0; i < 2; i++)
        #pragma unroll
        for (int j = 0; j < 4; j++)
            #pragma unroll
            for (int q = 0; q < 4; q++) acc[i][j][q] = 0.f;

    int kmax = t0 + 128;
    for (int k0 = 0; k0 < kmax; k0 += 32) {
        for (int g = tid; g < 768; g += 256) {
            const float* src; uint32_t *dh, *dl;
            if (g < 512) {
                int r = g >> 2, c8 = (g & 3) * 8;
                src = Pp + (long)r * TSEQ + k0 + c8;
                dh = Ph + r * PV_STR + c8 / 2; dl = Pl + r * PV_STR + c8 / 2;
            } else {
                int v = g - 512;
                int r = v >> 2, c8 = (v & 3) * 8;
                src = Vp + (long)r * TSEQ + k0 + c8;
                dh = Vh + r * PV_STR + c8 / 2; dl = Vl + r * PV_STR + c8 / 2;
            }
            float4 v0 = *(const float4*)src;
            float4 v1 = *(const float4*)(src + 4);
            uint4 hi, lo;
            split8(v0, v1, hi, lo);
            *(uint4*)dh = hi;
            *(uint4*)dl = lo;
        }
        __syncthreads();
        const uint32_t* Ap[3] = {Ph, Ph, Pl};
        const uint32_t* Bp[3] = {Vh, Vl, Vh};
        #pragma unroll
        for (int p = 0; p < 3; p++) {
            #pragma unroll
            for (int ks = 0; ks < 2; ks++) {
                int kk = ks * 8 + kt;
                unsigned af[2][4];
                #pragma unroll
                for (int i = 0; i < 2; i++) {
                    const uint32_t* base = Ap[p] + (mrow + i * 16) * PV_STR;
                    af[i][0] = base[kk];
                    af[i][1] = base[8 * PV_STR + kk];
                    af[i][2] = base[kk + 4];
                    af[i][3] = base[8 * PV_STR + kk + 4];
                }
                #pragma unroll
                for (int j = 0; j < 4; j++) {
                    const uint32_t* bb = Bp[p] + (nrow + j * 8) * PV_STR;
                    unsigned b0 = bb[kk], b1 = bb[kk + 4];
                    #pragma unroll
                    for (int i = 0; i < 2; i++)
                        mma_bf16x(acc[i][j], af[i][0], af[i][1], af[i][2], af[i][3], b0, b1);
                }
            }
        }
        __syncthreads();
    }
    #pragma unroll
    for (int i = 0; i < 2; i++) {
        int rr = t0 + wm * 32 + i * 16 + (lane >> 2);
        #pragma unroll
        for (int j = 0; j < 4; j++) {
            int cc = n * HDIM + wn * 32 + j * 8 + (lane & 3) * 2;
            #pragma unroll
            for (int q = 0; q < 2; q++) {
                O[(long)(b * TSEQ + rr + q * 8) * DMODEL + cc]     = tfr(acc[i][j][q * 2 + 0]);
                O[(long)(b * TSEQ + rr + q * 8) * DMODEL + cc + 1] = tfr(acc[i][j][q * 2 + 1]);
            }
        }
    }
}

// ---------------- orchestration ----------------
extern "C" void kernel_launch(void* const* d_in, const int* in_sizes, int n_in,
                              void* d_out, int out_size) {
    const int*   ids  = (const int*)d_in[0];
    const float* wte  = (const float*)d_in[1];
    const float* wpe  = (const float*)d_in[2];
    const float* Wq   = (const float*)d_in[3];
    const float* bq   = (const float*)d_in[4];
    const float* Wk   = (const float*)d_in[5];
    const float* bk   = (const float*)d_in[6];
    const float* Wv   = (const float*)d_in[7];
    const float* bv   = (const float*)d_in[8];
    const float* Wo   = (const float*)d_in[9];
    const float* bo   = (const float*)d_in[10];
    const float* gate = (const float*)d_in[11];
    const float* ln1g = (const float*)d_in[12];
    const float* ln1b = (const float*)d_in[13];
    const float* ln2g = (const float*)d_in[14];
    const float* ln2b = (const float*)d_in[15];
    const float* w1   = (const float*)d_in[16];
    const float* b1   = (const float*)d_in[17];
    const float* w2   = (const float*)d_in[18];
    const float* b2   = (const float*)d_in[19];
    const float* skw  = (const float*)d_in[20];
    const float* skb  = (const float*)d_in[21];
    const float* lnfg = (const float*)d_in[22];
    const float* lnfb = (const float*)d_in[23];
    float* out = (float*)d_out;

    float *h, *x, *o, *part, *ff, *qkv, *vt, *sc, *enc, *wot, *bos, *wqkv, *bqkv;
    float *w1c, *w2c, *skwc, *wtec;
    cudaGetSymbolAddress((void**)&h,    g_h);
    cudaGetSymbolAddress((void**)&x,    g_x);
    cudaGetSymbolAddress((void**)&o,    g_o);
    cudaGetSymbolAddress((void**)&part, g_part);
    cudaGetSymbolAddress((void**)&ff,   g_ff);
    cudaGetSymbolAddress((void**)&qkv,  g_qkv);
    cudaGetSymbolAddress((void**)&vt,   g_vt);
    cudaGetSymbolAddress((void**)&sc,   g_sc);
    cudaGetSymbolAddress((void**)&enc,  g_enc);
    cudaGetSymbolAddress((void**)&wot,  g_wot);
    cudaGetSymbolAddress((void**)&bos,  g_bos);
    cudaGetSymbolAddress((void**)&wqkv, g_wqkv);
    cudaGetSymbolAddress((void**)&bqkv, g_bqkv);
    cudaGetSymbolAddress((void**)&w1c,  g_w1c);
    cudaGetSymbolAddress((void**)&w2c,  g_w2c);
    cudaGetSymbolAddress((void**)&skwc, g_skwc);
    cudaGetSymbolAddress((void**)&wtec, g_wtec);

    cudaFuncSetAttribute(gemm_cp<0, true,  false, false, false>, cudaFuncAttributeMaxDynamicSharedMemorySize, GEMM_SMEM_BYTES);
    cudaFuncSetAttribute(gemm_cp<2, true,  false, false, true >, cudaFuncAttributeMaxDynamicSharedMemorySize, GEMM_SMEM_BYTES);
    cudaFuncSetAttribute(gemm_cp<0, false, false, false, false>, cudaFuncAttributeMaxDynamicSharedMemorySize, GEMM_SMEM_BYTES);
    cudaFuncSetAttribute(gemm_sk<false>, cudaFuncAttributeMaxDynamicSharedMemorySize, GEMM_SMEM_BYTES);
    cudaFuncSetAttribute(gemm_sk<true >, cudaFuncAttributeMaxDynamicSharedMemorySize, GEMM_SMEM_BYTES);
    cudaFuncSetAttribute(attn_scores_tc, cudaFuncAttributeMaxDynamicSharedMemorySize, SC_SMEM);

    dim3 gQKV(3 * DMODEL / 128, BT / 128);
    dim3 gSK(DMODEL / 128, BT / 128, 2);
    dim3 gF(FINNER / 128, BT / 128);
    dim3 gV(VOCAB / 128, BT / 128);
    int nAdd = (BT * DMODEL / 4 + 255) / 256;

    // keep gemm_cp (QKV, layer 0) as launch #4 for ncu visibility
    prep_wqkvb<<<(int)(((long)NLAYER * 3 * DMODEL * DMODEL + 255) / 256), 256>>>(
        Wq, Wk, Wv, bq, bk, bv, wqkv, bqkv);
    embed_k<<<(BT * DMODEL + 255) / 256, 256>>>(ids, wte, wpe, h);
    layernorm_k<<<BT, 256>>>(h, x, ln1g, ln1b);

    for (int i = 0; i < NLAYER; i++) {
        gemm_cp<0, true, false, false, false><<<gQKV, 256, GEMM_SMEM_BYTES>>>(
            x, wqkv + (long)i * 3 * DMODEL * DMODEL, bqkv + i * 3 * DMODEL, nullptr, qkv,
            BT, 3 * DMODEL, DMODEL, DMODEL, DMODEL, 3 * DMODEL);

        attn_scores_tc<<<dim3(TSEQ / 128, TSEQ / 128, BBATCH * NHEAD), 256, SC_SMEM>>>(qkv, sc);
        softmax_rows<<<dim3(TSEQ, BBATCH * NHEAD), 128>>>(sc);
        transpose_v<<<dim3(TSEQ / 32, HDIM / 32, BBATCH * NHEAD), dim3(32, 8)>>>(qkv, vt);
        attn_pv_tc<<<dim3(TSEQ / 128, BBATCH * NHEAD), 256>>>(sc, vt, o);

        if (i == 0) {
            prep_wot<<<(NLAYER * DMODEL * DMODEL + 255) / 256, 256>>>(Wo, gate, wot);
            prep_bos<<<(NLAYER * DMODEL + 255) / 256, 256>>>(bo, gate, bos);
            long n1 = (long)NLAYER * FINNER * DMODEL;
            tf32_copy<<<(int)((n1 / 4 + 255) / 256), 256>>>(w1, w1c, n1);
            tf32_copy<<<(int)((n1 / 4 + 255) / 256), 256>>>(w2, w2c, n1);
            long n2 = (long)NLAYER * DMODEL * 2 * DMODEL;
            tf32_copy<<<(int)((n2 / 4 + 255) / 256), 256>>>(skw, skwc, n2);
            long n3 = (long)VOCAB * DMODEL;
            tf32_copy<<<(int)((n3 / 4 + 255) / 256), 256>>>(wte, wtec, n3);
        }

        gemm_sk<false><<<gSK, 256, GEMM_SMEM_BYTES>>>(
            o, o + 512, wot + (long)i * DMODEL * DMODEL, part,
            512, DMODEL, DMODEL, 512);
        add_ln<true><<<BT, 256>>>(part, bos + i * DMODEL, h, x,
                                  ln2g + i * DMODEL, ln2b + i * DMODEL);
        if (i < NLAYER / 2)
            tf32_copy<<<nAdd, 256>>>(h, enc + (long)i * BT * DMODEL, (long)BT * DMODEL);

        gemm_cp<2, true, false, false, true><<<gF, 256, GEMM_SMEM_BYTES>>>(
            x, w1c + (long)i * FINNER * DMODEL, b1 + i * FINNER, nullptr, ff,
            BT, FINNER, DMODEL, DMODEL, DMODEL, FINNER);
        gemm_sk<false><<<gSK, 256, GEMM_SMEM_BYTES>>>(
            ff, ff + 2048, w2c + (long)i * DMODEL * FINNER, part,
            2048, FINNER, FINNER, 2048);

        if (i < NLAYER / 2) {
            add_ln<true><<<BT, 256>>>(part, b2 + i * DMODEL, h, x,
                                      ln1g + (i + 1) * DMODEL, ln1b + (i + 1) * DMODEL);
        } else {
            add2_k<<<nAdd, 256>>>(part, b2 + i * DMODEL, h);
            int el = NLAYER - i - 1;
            const float* sw = skwc + (long)i * DMODEL * 2 * DMODEL;
            gemm_sk<true><<<gSK, 256, GEMM_SMEM_BYTES>>>(
                h, enc + (long)el * BT * DMODEL, sw, part,
                DMODEL, DMODEL, 2 * DMODEL, DMODEL);
            if (i + 1 < NLAYER) {
                add_ln<false><<<BT, 256>>>(part, skb + i * DMODEL, h, x,
                                           ln1g + (i + 1) * DMODEL, ln1b + (i + 1) * DMODEL);
            } else {
                add_ln<false><<<BT, 256>>>(part, skb + i * DMODEL, h, x, lnfg, lnfb);
            }
        }
    }

    gemm_cp<0, false, false, false, false><<<gV, 256, GEMM_SMEM_BYTES>>>(
        x, wtec, nullptr, nullptr, out, BT, VOCAB, DMODEL, DMODEL, DMODEL, VOCAB);
}

// round 14
// speedup vs baseline: 1.0305x; 1.0305x over previous
#include <cuda_runtime.h>
#include <cuda_bf16.h>
#include <math.h>
#include <stdint.h>

// Model dims
#define BBATCH 4
#define TSEQ   512
#define BT     2048
#define DMODEL 1024
#define NHEAD  16
#define HDIM   64
#define FINNER 4096
#define VOCAB  32000
#define NLAYER 8

typedef __nv_bfloat16 bf16;

// ---------------- scratch ----------------
__device__ float g_h   [BT * DMODEL];
__device__ float g_x   [BT * DMODEL];
__device__ float g_o   [BT * DMODEL];
__device__ float g_part[2 * BT * DMODEL];
__device__ float g_ff  [BT * FINNER];
__device__ float g_qkv [BT * 3 * DMODEL];
__device__ float g_vt  [(size_t)BBATCH * NHEAD * HDIM * TSEQ];
__device__ float g_sc  [(size_t)BBATCH * NHEAD * TSEQ * TSEQ];
__device__ float g_enc [4 * BT * DMODEL];
__device__ float g_wot [NLAYER * DMODEL * DMODEL];
__device__ float g_bos [NLAYER * DMODEL];
__device__ float g_wqkv[(size_t)NLAYER * 3 * DMODEL * DMODEL];
__device__ float g_bqkv[NLAYER * 3 * DMODEL];
__device__ float g_w1c [(size_t)NLAYER * FINNER * DMODEL];
__device__ float g_w2c [(size_t)NLAYER * DMODEL * FINNER];
__device__ float g_skwc[(size_t)NLAYER * DMODEL * 2 * DMODEL];
__device__ float g_wtec[(size_t)VOCAB * DMODEL];

// ---------------- helpers ----------------
__device__ __forceinline__ unsigned f2tf(float x) {
    unsigned r; asm("cvt.rna.tf32.f32 %0, %1;" : "=r"(r) : "f"(x)); return r;
}
__device__ __forceinline__ float tfr(float x) { return __uint_as_float(f2tf(x)); }
__device__ __forceinline__ uint32_t s2u(const void* p) {
    uint32_t a;
    asm("{ .reg .u64 t; cvta.to.shared.u64 t, %1; cvt.u32.u64 %0, t; }" : "=r"(a) : "l"(p));
    return a;
}
#define CP_ASYNC16(dst, src) \
    asm volatile("cp.async.cg.shared.global [%0], [%1], 16;" :: "r"(dst), "l"(src))
#define CP_COMMIT() asm volatile("cp.async.commit_group;")
#define CP_WAIT0()  asm volatile("cp.async.wait_group 0;")
#define CP_WAIT1()  asm volatile("cp.async.wait_group 1;")

__device__ __forceinline__ void mma_tf32(float c[4], unsigned a0, unsigned a1,
                                         unsigned a2, unsigned a3,
                                         unsigned b0, unsigned b1) {
    asm volatile(
        "mma.sync.aligned.m16n8k8.row.col.f32.tf32.tf32.f32 "
        "{%0,%1,%2,%3}, {%4,%5,%6,%7}, {%8,%9}, {%0,%1,%2,%3};"
        : "+f"(c[0]), "+f"(c[1]), "+f"(c[2]), "+f"(c[3])
        : "r"(a0), "r"(a1), "r"(a2), "r"(a3), "r"(b0), "r"(b1));
}
__device__ __forceinline__ void mma_bf16x(float c[4], unsigned a0, unsigned a1,
                                          unsigned a2, unsigned a3,
                                          unsigned b0, unsigned b1) {
    asm volatile(
        "mma.sync.aligned.m16n8k16.row.col.f32.bf16.bf16.f32 "
        "{%0,%1,%2,%3}, {%4,%5,%6,%7}, {%8,%9}, {%0,%1,%2,%3};"
        : "+f"(c[0]), "+f"(c[1]), "+f"(c[2]), "+f"(c[3])
        : "r"(a0), "r"(a1), "r"(a2), "r"(a3), "r"(b0), "r"(b1));
}
__device__ __forceinline__ void split8(float4 v0, float4 v1, uint4& hi, uint4& lo) {
    float f[8] = {v0.x, v0.y, v0.z, v0.w, v1.x, v1.y, v1.z, v1.w};
    uint32_t hs[8], ls[8];
    #pragma unroll
    for (int i = 0; i < 8; i++) {
        bf16 h = __float2bfloat16(f[i]);
        bf16 l = __float2bfloat16(f[i] - __bfloat162float(h));
        hs[i] = *(unsigned short*)&h;
        ls[i] = *(unsigned short*)&l;
    }
    hi = make_uint4(hs[0] | (hs[1] << 16), hs[2] | (hs[3] << 16),
                    hs[4] | (hs[5] << 16), hs[6] | (hs[7] << 16));
    lo = make_uint4(ls[0] | (ls[1] << 16), ls[2] | (ls[3] << 16),
                    ls[4] | (ls[5] << 16), ls[6] | (ls[7] << 16));
}

// ---------------- prep kernels ----------------
__global__ void tf32_copy(const float* __restrict__ in, float* __restrict__ out, long n) {
    long i = ((long)blockIdx.x * 256 + threadIdx.x) * 4;
    if (i >= n) return;
    float4 v = *(const float4*)(in + i);
    v.x = tfr(v.x); v.y = tfr(v.y); v.z = tfr(v.z); v.w = tfr(v.w);
    *(float4*)(out + i) = v;
}

__global__ void prep_wqkvb(const float* __restrict__ Wq, const float* __restrict__ Wk,
                           const float* __restrict__ Wv,
                           const float* __restrict__ bq, const float* __restrict__ bk,
                           const float* __restrict__ bv,
                           float* __restrict__ W, float* __restrict__ bias) {
    long idx = (long)blockIdx.x * 256 + threadIdx.x;
    if (idx >= (long)NLAYER * 3 * DMODEL * DMODEL) return;
    int l = (int)(idx / (3L * DMODEL * DMODEL));
    long rem = idx - (long)l * 3 * DMODEL * DMODEL;
    int r = (int)(rem >> 10), d = (int)(rem & 1023);
    int sel = r >> 10, rn = r & 1023;
    const float* src = sel == 0 ? Wq : (sel == 1 ? Wk : Wv);
    W[idx] = tfr(src[((long)l * DMODEL + rn) * DMODEL + d]);
    if (idx < NLAYER * 3 * DMODEL) {
        int lb = (int)(idx / (3 * DMODEL)), rb = (int)(idx % (3 * DMODEL));
        int selb = rb >> 10, rnb = rb & 1023;
        const float* b = selb == 0 ? bq : (selb == 1 ? bk : bv);
        bias[idx] = b[lb * DMODEL + rnb];
    }
}

__global__ void prep_wot(const float* __restrict__ Wo, const float* __restrict__ gate,
                         float* __restrict__ wot) {
    long idx = (long)blockIdx.x * 256 + threadIdx.x;
    if (idx >= (long)NLAYER * DMODEL * DMODEL) return;
    int l = (int)(idx >> 20);
    int d = (int)((idx >> 10) & 1023);
    int c = (int)(idx & 1023);
    int n = c >> 6, hh = c & 63;
    wot[idx] = tfr(Wo[((long)(l * NHEAD + n)) * (DMODEL * HDIM) + (long)d * HDIM + hh]
                   * gate[l * NHEAD + n]);
}

__global__ void prep_bos(const float* __restrict__ bo, const float* __restrict__ gate,
                         float* __restrict__ bos) {
    int idx = blockIdx.x * 256 + threadIdx.x;
    if (idx >= NLAYER * DMODEL) return;
    int l = idx >> 10, d = idx & 1023;
    float s = 0.f;
    for (int n = 0; n < NHEAD; n++)
        s += gate[l * NHEAD + n] * bo[(long)(l * NHEAD + n) * DMODEL + d];
    bos[idx] = s;
}

__global__ void embed_k(const int* __restrict__ ids, const float* __restrict__ wte,
                        const float* __restrict__ wpe, float* __restrict__ h) {
    long idx = (long)blockIdx.x * 256 + threadIdx.x;
    if (idx >= (long)BT * DMODEL) return;
    int bt = (int)(idx >> 10), d = (int)(idx & 1023);
    int t = bt & (TSEQ - 1);
    h[idx] = wte[(long)ids[bt] * DMODEL + d] + wpe[(long)t * DMODEL + d];
}

// ---------------- layernorm (layer-0 entry only) ----------------
__global__ void layernorm_k(const float* __restrict__ in, float* __restrict__ out,
                            const float* __restrict__ g, const float* __restrict__ b) {
    int row = blockIdx.x;
    const float* x = in + (long)row * DMODEL;
    float* y = out + (long)row * DMODEL;
    __shared__ float red[256];
    int tid = threadIdx.x;
    float s = 0.f;
    for (int i = tid; i < DMODEL; i += 256) s += x[i];
    red[tid] = s; __syncthreads();
    for (int o = 128; o > 0; o >>= 1) { if (tid < o) red[tid] += red[tid + o]; __syncthreads(); }
    float mean = red[0] * (1.0f / DMODEL);
    __syncthreads();
    float v = 0.f;
    for (int i = tid; i < DMODEL; i += 256) { float d = x[i] - mean; v += d * d; }
    red[tid] = v; __syncthreads();
    for (int o = 128; o > 0; o >>= 1) { if (tid < o) red[tid] += red[tid + o]; __syncthreads(); }
    float inv = rsqrtf(red[0] * (1.0f / DMODEL) + 1e-5f);
    for (int i = tid; i < DMODEL; i += 256)
        y[i] = tfr((x[i] - mean) * inv * g[i] + b[i]);
}

// ---------------- fused: h = (ADDH? h : 0) + p0 + p1 + bias;  x = LN(h) ------
template<bool ADDH>
__global__ void add_ln(const float* __restrict__ part, const float* __restrict__ bias,
                       float* __restrict__ h, float* __restrict__ x,
                       const float* __restrict__ g, const float* __restrict__ b) {
    int row = blockIdx.x;
    int tid = threadIdx.x;
    __shared__ float buf[DMODEL];
    __shared__ float red[256];
    const float* p0 = part + (long)row * DMODEL;
    const float* p1 = part + (long)BT * DMODEL + (long)row * DMODEL;
    float* hp = h + (long)row * DMODEL;
    float* xp = x + (long)row * DMODEL;
    float s = 0.f;
    for (int i = tid; i < DMODEL; i += 256) {
        float v = p0[i] + p1[i] + bias[i];
        if (ADDH) v += hp[i];
        buf[i] = v;
        hp[i] = v;
        s += v;
    }
    red[tid] = s; __syncthreads();
    for (int o = 128; o > 0; o >>= 1) { if (tid < o) red[tid] += red[tid + o]; __syncthreads(); }
    float mean = red[0] * (1.0f / DMODEL);
    __syncthreads();
    float v2 = 0.f;
    for (int i = tid; i < DMODEL; i += 256) { float d = buf[i] - mean; v2 += d * d; }
    red[tid] = v2; __syncthreads();
    for (int o = 128; o > 0; o >>= 1) { if (tid < o) red[tid] += red[tid + o]; __syncthreads(); }
    float inv = rsqrtf(red[0] * (1.0f / DMODEL) + 1e-5f);
    for (int i = tid; i < DMODEL; i += 256)
        xp[i] = tfr((buf[i] - mean) * inv * g[i] + b[i]);
}

__global__ void add2_k(const float* __restrict__ part, const float* __restrict__ bias,
                       float* __restrict__ out) {
    long i = ((long)blockIdx.x * 256 + threadIdx.x) * 4;
    if (i >= (long)BT * DMODEL) return;
    int n = (int)(i & (DMODEL - 1));
    float4 p0 = *(const float4*)(part + i);
    float4 p1 = *(const float4*)(part + (long)BT * DMODEL + i);
    float4 b4 = *(const float4*)(bias + n);
    float4 r4 = *(const float4*)(out + i);
    float4 v;
    v.x = p0.x + p1.x + b4.x + r4.x;
    v.y = p0.y + p1.y + b4.y + r4.y;
    v.z = p0.z + p1.z + b4.z + r4.z;
    v.w = p0.w + p1.w + b4.w + r4.w;
    *(float4*)(out + i) = v;
}

// ---------------- tf32 GEMM, 2-stage cp.async, b-prefetch pipeline ----------
#define SMEM_STRIDE 36
#define TILE_U (128 * SMEM_STRIDE)
#define GEMM_SMEM_BYTES (4 * TILE_U * 4)

// inner product over one 32-K chunk with 1-deep B-fragment software pipeline
template<bool CVTA>
__device__ __forceinline__ void mma_chunk(
    const unsigned* __restrict__ Ab, const unsigned* __restrict__ Bb,
    float acc[2][8][4], int mrow, int nrow, int kt) {
    #pragma unroll
    for (int ks = 0; ks < 4; ks++) {
        int kk = ks * 8 + kt;
        unsigned af[2][4];
        #pragma unroll
        for (int i = 0; i < 2; i++) {
            const unsigned* base = Ab + (mrow + i * 16) * SMEM_STRIDE;
            af[i][0] = base[kk];
            af[i][1] = base[8 * SMEM_STRIDE + kk];
            af[i][2] = base[kk + 4];
            af[i][3] = base[8 * SMEM_STRIDE + kk + 4];
            if (CVTA) {
                #pragma unroll
                for (int q = 0; q < 4; q++) af[i][q] = f2tf(__uint_as_float(af[i][q]));
            }
        }
        // software-pipelined B loads: fetch j+1 before consuming j
        const unsigned* bp0 = Bb + nrow * SMEM_STRIDE;
        unsigned cb0 = bp0[kk], cb1 = bp0[kk + 4];
        #pragma unroll
        for (int j = 0; j < 8; j++) {
            unsigned nb0 = 0, nb1 = 0;
            if (j < 7) {
                const unsigned* bp = Bb + (nrow + (j + 1) * 8) * SMEM_STRIDE;
                nb0 = bp[kk];
                nb1 = bp[kk + 4];
            }
            mma_tf32(acc[0][j], af[0][0], af[0][1], af[0][2], af[0][3], cb0, cb1);
            mma_tf32(acc[1][j], af[1][0], af[1][1], af[1][2], af[1][3], cb0, cb1);
            cb0 = nb0; cb1 = nb1;
        }
    }
}

template<int EPI, bool BIAS, bool RES, bool CVTA, bool ROUND>
__global__ __launch_bounds__(256, 2) void gemm_cp(
    const float* __restrict__ A, const float* __restrict__ Bm,
    const float* __restrict__ bias, const float* __restrict__ res,
    float* __restrict__ C, int M, int N, int K, int lda, int ldb, int ldc) {
    extern __shared__ float sm[];
    float* As = sm;
    float* Bs = sm + 2 * TILE_U;
    const uint32_t AsU = s2u(As), BsU = s2u(Bs);

    int tid = threadIdx.x, lane = tid & 31, warp = tid >> 5;
    int wm = warp & 3, wn = warp >> 2;
    int m0 = blockIdx.y * 128, n0 = blockIdx.x * 128;
    const float* Ag = A + (long)m0 * lda;
    const float* Bg = Bm + (long)n0 * ldb;

    const float* Asrc[4]; const float* Bsrc[4];
    uint32_t Adst[4], Bdst[4];
    #pragma unroll
    for (int i = 0; i < 4; i++) {
        int idx = tid + i * 256;
        int r = idx >> 3, c = (idx & 7) * 4;
        Asrc[i] = Ag + (long)r * lda + c;
        Bsrc[i] = Bg + (long)r * ldb + c;
        Adst[i] = AsU + (uint32_t)(r * SMEM_STRIDE + c) * 4;
        Bdst[i] = BsU + (uint32_t)(r * SMEM_STRIDE + c) * 4;
    }

    float acc[2][8][4];
    #pragma unroll
    for (int i = 0; i < 2; i++)
        #pragma unroll
        for (int j = 0; j < 8; j++)
            #pragma unroll
            for (int q = 0; q < 4; q++) acc[i][j][q] = 0.f;

    int mrow = wm * 32 + (lane >> 2);
    int nrow = wn * 64 + (lane >> 2);
    int kt = lane & 3;

    #pragma unroll
    for (int i = 0; i < 4; i++) {
        CP_ASYNC16(Adst[i], Asrc[i]);
        CP_ASYNC16(Bdst[i], Bsrc[i]);
    }
    CP_COMMIT();

    int p = 0;
    for (int k0 = 0; k0 < K; k0 += 32) {
        if (k0 + 32 < K) {
            uint32_t po = (uint32_t)((p ^ 1) * TILE_U) * 4;
            #pragma unroll
            for (int i = 0; i < 4; i++) {
                CP_ASYNC16(Adst[i] + po, Asrc[i] + k0 + 32);
                CP_ASYNC16(Bdst[i] + po, Bsrc[i] + k0 + 32);
            }
            CP_COMMIT();
            CP_WAIT1();
        } else {
            CP_WAIT0();
        }
        __syncthreads();
        mma_chunk<CVTA>((const unsigned*)(As + p * TILE_U),
                        (const unsigned*)(Bs + p * TILE_U), acc, mrow, nrow, kt);
        __syncthreads();
        p ^= 1;
    }

    #pragma unroll
    for (int i = 0; i < 2; i++) {
        int m = m0 + wm * 32 + i * 16 + (lane >> 2);
        #pragma unroll
        for (int j = 0; j < 8; j++) {
            int n = n0 + wn * 64 + j * 8 + (lane & 3) * 2;
            #pragma unroll
            for (int q = 0; q < 2; q++) {
                int mm = m + q * 8;
                float v0 = acc[i][j][q * 2 + 0];
                float v1 = acc[i][j][q * 2 + 1];
                if (BIAS) { v0 += bias[n]; v1 += bias[n + 1]; }
                if (RES)  { v0 += res[(long)mm * ldc + n]; v1 += res[(long)mm * ldc + n + 1]; }
                if (EPI == 2) {
                    v0 = 0.5f * v0 * (1.0f + erff(v0 * 0.70710678118654752f));
                    v1 = 0.5f * v1 * (1.0f + erff(v1 * 0.70710678118654752f));
                }
                if (ROUND) { v0 = tfr(v0); v1 = tfr(v1); }
                C[(long)mm * ldc + n]     = v0;
                C[(long)mm * ldc + n + 1] = v1;
            }
        }
    }
}

// ---------------- split-K / dual-source tf32 GEMM ----------------
template<bool CVTA>
__global__ __launch_bounds__(256, 2) void gemm_sk(
    const float* __restrict__ A0, const float* __restrict__ A1,
    const float* __restrict__ Bm, float* __restrict__ part,
    int K2, int lda, int ldb, int boff) {
    extern __shared__ float sm[];
    float* As = sm;
    float* Bs = sm + 2 * TILE_U;
    const uint32_t AsU = s2u(As), BsU = s2u(Bs);

    int tid = threadIdx.x, lane = tid & 31, warp = tid >> 5;
    int wm = warp & 3, wn = warp >> 2;
    int m0 = blockIdx.y * 128, n0 = blockIdx.x * 128;
    int z = blockIdx.z;
    const float* Ag = (z ? A1 : A0) + (long)m0 * lda;
    const float* Bg = Bm + (long)n0 * ldb + (long)z * boff;
    float* C = part + (long)z * BT * DMODEL;

    const float* Asrc[4]; const float* Bsrc[4];
    uint32_t Adst[4], Bdst[4];
    #pragma unroll
    for (int i = 0; i < 4; i++) {
        int idx = tid + i * 256;
        int r = idx >> 3, c = (idx & 7) * 4;
        Asrc[i] = Ag + (long)r * lda + c;
        Bsrc[i] = Bg + (long)r * ldb + c;
        Adst[i] = AsU + (uint32_t)(r * SMEM_STRIDE + c) * 4;
        Bdst[i] = BsU + (uint32_t)(r * SMEM_STRIDE + c) * 4;
    }

    float acc[2][8][4];
    #pragma unroll
    for (int i = 0; i < 2; i++)
        #pragma unroll
        for (int j = 0; j < 8; j++)
            #pragma unroll
            for (int q = 0; q < 4; q++) acc[i][j][q] = 0.f;

    int mrow = wm * 32 + (lane >> 2);
    int nrow = wn * 64 + (lane >> 2);
    int kt = lane & 3;

    #pragma unroll
    for (int i = 0; i < 4; i++) {
        CP_ASYNC16(Adst[i], Asrc[i]);
        CP_ASYNC16(Bdst[i], Bsrc[i]);
    }
    CP_COMMIT();

    int p = 0;
    for (int k0 = 0; k0 < K2; k0 += 32) {
        if (k0 + 32 < K2) {
            uint32_t po = (uint32_t)((p ^ 1) * TILE_U) * 4;
            #pragma unroll
            for (int i = 0; i < 4; i++) {
                CP_ASYNC16(Adst[i] + po, Asrc[i] + k0 + 32);
                CP_ASYNC16(Bdst[i] + po, Bsrc[i] + k0 + 32);
            }
            CP_COMMIT();
            CP_WAIT1();
        } else {
            CP_WAIT0();
        }
        __syncthreads();
        mma_chunk<CVTA>((const unsigned*)(As + p * TILE_U),
                        (const unsigned*)(Bs + p * TILE_U), acc, mrow, nrow, kt);
        __syncthreads();
        p ^= 1;
    }

    #pragma unroll
    for (int i = 0; i < 2; i++) {
        int m = m0 + wm * 32 + i * 16 + (lane >> 2);
        #pragma unroll
        for (int j = 0; j < 8; j++) {
            int n = n0 + wn * 64 + j * 8 + (lane & 3) * 2;
            #pragma unroll
            for (int q = 0; q < 2; q++) {
                int mm = m + q * 8;
                C[(long)mm * DMODEL + n]     = acc[i][j][q * 2 + 0];
                C[(long)mm * DMODEL + n + 1] = acc[i][j][q * 2 + 1];
            }
        }
    }
}

// ---------------- attention scores: bf16 3-pass mma ----------------
#define SC_STR 36
#define SC_PLANE (128 * SC_STR)
#define SC_SMEM (4 * SC_PLANE * 4)

__global__ __launch_bounds__(256) void attn_scores_tc(
    const float* __restrict__ qkv, float* __restrict__ S) {
    int bh = blockIdx.z;
    int b = bh >> 4, n = bh & 15;
    int s0 = blockIdx.x * 128, t0 = blockIdx.y * 128;
    if (s0 > t0) return;
    extern __shared__ uint32_t smq[];
    uint32_t* Qh = smq;
    uint32_t* Ql = smq + SC_PLANE;
    uint32_t* Kh = smq + 2 * SC_PLANE;
    uint32_t* Kl = smq + 3 * SC_PLANE;
    int tid = threadIdx.x, lane = tid & 31, warp = tid >> 5;
    const float* Qp = qkv + ((long)(b * TSEQ + t0)) * (3 * DMODEL) + n * HDIM;
    const float* Kp = qkv + ((long)(b * TSEQ + s0)) * (3 * DMODEL) + DMODEL + n * HDIM;
    for (int g = tid; g < 2048; g += 256) {
        int isK = g >= 1024;
        int gg = g & 1023;
        int r = gg >> 3, c8 = (gg & 7) * 8;
        const float* src = (isK ? Kp : Qp) + (long)r * (3 * DMODEL) + c8;
        float4 v0 = *(const float4*)src;
        float4 v1 = *(const float4*)(src + 4);
        uint4 hi, lo;
        split8(v0, v1, hi, lo);
        int off = r * SC_STR + c8 / 2;
        *(uint4*)((isK ? Kh : Qh) + off) = hi;
        *(uint4*)((isK ? Kl : Ql) + off) = lo;
    }
    __syncthreads();

    int wm = warp & 3, wn = warp >> 2;
    int mrow = wm * 32 + (lane >> 2);
    int nrow = wn * 64 + (lane >> 2);
    int kt = lane & 3;
    float acc[2][8][4];
    #pragma unroll
    for (int i = 0; i < 2; i++)
        #pragma unroll
        for (int j = 0; j < 8; j++)
            #pragma unroll
            for (int q = 0; q < 4; q++) acc[i][j][q] = 0.f;

    const uint32_t* Ap[3] = {Qh, Qh, Ql};
    const uint32_t* Bp[3] = {Kh, Kl, Kh};
    #pragma unroll
    for (int p = 0; p < 3; p++) {
        #pragma unroll
        for (int ks = 0; ks < 4; ks++) {
            int kk = ks * 8 + kt;
            unsigned af[2][4];
            #pragma unroll
            for (int i = 0; i < 2; i++) {
                const uint32_t* base = Ap[p] + (mrow + i * 16) * SC_STR;
                af[i][0] = base[kk];
                af[i][1] = base[8 * SC_STR + kk];
                af[i][2] = base[kk + 4];
                af[i][3] = base[8 * SC_STR + kk + 4];
            }
            #pragma unroll
            for (int j = 0; j < 8; j++) {
                const uint32_t* bb = Bp[p] + (nrow + j * 8) * SC_STR;
                unsigned b0 = bb[kk], b1 = bb[kk + 4];
                #pragma unroll
                for (int i = 0; i < 2; i++)
                    mma_bf16x(acc[i][j], af[i][0], af[i][1], af[i][2], af[i][3], b0, b1);
            }
        }
    }
    float* Sp = S + ((long)bh * TSEQ + t0) * TSEQ + s0;
    #pragma unroll
    for (int i = 0; i < 2; i++) {
        int rr = wm * 32 + i * 16 + (lane >> 2);
        #pragma unroll
        for (int j = 0; j < 8; j++) {
            int cc = wn * 64 + j * 8 + (lane & 3) * 2;
            #pragma unroll
            for (int q = 0; q < 2; q++) {
                Sp[(long)(rr + q * 8) * TSEQ + cc]     = acc[i][j][q * 2 + 0] * 0.125f;
                Sp[(long)(rr + q * 8) * TSEQ + cc + 1] = acc[i][j][q * 2 + 1] * 0.125f;
            }
        }
    }
}

// ---------------- softmax ----------------
__global__ void softmax_rows(float* __restrict__ S) {
    int t = blockIdx.x, bh = blockIdx.y;
    float* row = S + ((long)bh * TSEQ + t) * TSEQ;
    int len = t + 1;
    __shared__ float red[128];
    int tid = threadIdx.x;
    float mx = -1e30f;
    for (int s = tid; s < len; s += 128) mx = fmaxf(mx, row[s]);
    red[tid] = mx; __syncthreads();
    for (int o = 64; o > 0; o >>= 1) { if (tid < o) red[tid] = fmaxf(red[tid], red[tid + o]); __syncthreads(); }
    mx = red[0]; __syncthreads();
    float sum = 0.f;
    for (int s = tid; s < len; s += 128) { float e = __expf(row[s] - mx); row[s] = e; sum += e; }
    red[tid] = sum; __syncthreads();
    for (int o = 64; o > 0; o >>= 1) { if (tid < o) red[tid] += red[tid + o]; __syncthreads(); }
    float inv = 1.0f / red[0];
    for (int s = tid; s < len; s += 128) row[s] *= inv;
    for (int s = len + tid; s < TSEQ; s += 128) row[s] = 0.0f;
}

// ---------------- V transpose ----------------
__global__ void transpose_v(const float* __restrict__ qkv, float* __restrict__ Vt) {
    int bh = blockIdx.z;
    int b = bh >> 4, n = bh & 15;
    int tt = blockIdx.x * 32, dd = blockIdx.y * 32;
    __shared__ float tile[32][33];
    int tx = threadIdx.x, ty = threadIdx.y;
    #pragma unroll
    for (int i = 0; i < 4; i++) {
        int t = tt + ty + i * 8;
        tile[ty + i * 8][tx] =
            qkv[((long)(b * TSEQ + t)) * (3 * DMODEL) + 2 * DMODEL + n * HDIM + dd + tx];
    }
    __syncthreads();
    #pragma unroll
    for (int i = 0; i < 4; i++) {
        int d = dd + ty + i * 8;
        Vt[((long)bh * HDIM + d) * TSEQ + tt + tx] = tile[tx][ty + i * 8];
    }
}

// ---------------- attention PV: bf16 3-pass mma (tf32-rounded output) -------
#define PV_STR 20

__global__ __launch_bounds__(256) void attn_pv_tc(
    const float* __restrict__ P, const float* __restrict__ Vt, float* __restrict__ O) {
    int bh = blockIdx.y;
    int b = bh >> 4, n = bh & 15;
    int t0 = blockIdx.x * 128;
    __shared__ uint32_t Ph[128 * PV_STR], Pl[128 * PV_STR];
    __shared__ uint32_t Vh[64 * PV_STR],  Vl[64 * PV_STR];
    int tid = threadIdx.x, lane = tid & 31, warp = tid >> 5;
    int wm = warp & 3, wn = warp >> 2;
    int mrow = wm * 32 + (lane >> 2);
    int nrow = wn * 32 + (lane >> 2);
    int kt = lane & 3;
    const float* Pp = P + ((long)bh * TSEQ + t0) * TSEQ;
    const float* Vp = Vt + (long)bh * HDIM * TSEQ;

    float acc[2][4][4];
    #pragma unroll
    for (int i = 0; i < 2; i++)
        #pragma unroll
        for (int j = 0; j < 4; j++)
            #pragma unroll
            for (int q = 0; q < 4; q++) acc[i][j][q] = 0.f;

    int kmax = t0 + 128;
    for (int k0 = 0; k0 < kmax; k0 += 32) {
        for (int g = tid; g < 768; g += 256) {
            const float* src; uint32_t *dh, *dl;
            if (g < 512) {
                int r = g >> 2, c8 = (g & 3) * 8;
                src = Pp + (long)r * TSEQ + k0 + c8;
                dh = Ph + r * PV_STR + c8 / 2; dl = Pl + r * PV_STR + c8 / 2;
            } else {
                int v = g - 512;
                int r = v >> 2, c8 = (v & 3) * 8;
                src = Vp + (long)r * TSEQ + k0 + c8;
                dh = Vh + r * PV_STR + c8 / 2; dl = Vl + r * PV_STR + c8 / 2;
            }
            float4 v0 = *(const float4*)src;
            float4 v1 = *(const float4*)(src + 4);
            uint4 hi, lo;
            split8(v0, v1, hi, lo);
            *(uint4*)dh = hi;
            *(uint4*)dl = lo;
        }
        __syncthreads();
        const uint32_t* Ap[3] = {Ph, Ph, Pl};
        const uint32_t* Bp[3] = {Vh, Vl, Vh};
        #pragma unroll
        for (int p = 0; p < 3; p++) {
            #pragma unroll
            for (int ks = 0; ks < 2; ks++) {
                int kk = ks * 8 + kt;
                unsigned af[2][4];
                #pragma unroll
                for (int i = 0; i < 2; i++) {
                    const uint32_t* base = Ap[p] + (mrow + i * 16) * PV_STR;
                    af[i][0] = base[kk];
                    af[i][1] = base[8 * PV_STR + kk];
                    af[i][2] = base[kk + 4];
                    af[i][3] = base[8 * PV_STR + kk + 4];
                }
                #pragma unroll
                for (int j = 0; j < 4; j++) {
                    const uint32_t* bb = Bp[p] + (nrow + j * 8) * PV_STR;
                    unsigned b0 = bb[kk], b1 = bb[kk + 4];
                    #pragma unroll
                    for (int i = 0; i < 2; i++)
                        mma_bf16x(acc[i][j], af[i][0], af[i][1], af[i][2], af[i][3], b0, b1);
                }
            }
        }
        __syncthreads();
    }
    #pragma unroll
    for (int i = 0; i < 2; i++) {
        int rr = t0 + wm * 32 + i * 16 + (lane >> 2);
        #pragma unroll
        for (int j = 0; j < 4; j++) {
            int cc = n * HDIM + wn * 32 + j * 8 + (lane & 3) * 2;
            #pragma unroll
            for (int q = 0; q < 2; q++) {
                O[(long)(b * TSEQ + rr + q * 8) * DMODEL + cc]     = tfr(acc[i][j][q * 2 + 0]);
                O[(long)(b * TSEQ + rr + q * 8) * DMODEL + cc + 1] = tfr(acc[i][j][q * 2 + 1]);
            }
        }
    }
}

// ---------------- orchestration ----------------
extern "C" void kernel_launch(void* const* d_in, const int* in_sizes, int n_in,
                              void* d_out, int out_size) {
    const int*   ids  = (const int*)d_in[0];
    const float* wte  = (const float*)d_in[1];
    const float* wpe  = (const float*)d_in[2];
    const float* Wq   = (const float*)d_in[3];
    const float* bq   = (const float*)d_in[4];
    const float* Wk   = (const float*)d_in[5];
    const float* bk   = (const float*)d_in[6];
    const float* Wv   = (const float*)d_in[7];
    const float* bv   = (const float*)d_in[8];
    const float* Wo   = (const float*)d_in[9];
    const float* bo   = (const float*)d_in[10];
    const float* gate = (const float*)d_in[11];
    const float* ln1g = (const float*)d_in[12];
    const float* ln1b = (const float*)d_in[13];
    const float* ln2g = (const float*)d_in[14];
    const float* ln2b = (const float*)d_in[15];
    const float* w1   = (const float*)d_in[16];
    const float* b1   = (const float*)d_in[17];
    const float* w2   = (const float*)d_in[18];
    const float* b2   = (const float*)d_in[19];
    const float* skw  = (const float*)d_in[20];
    const float* skb  = (const float*)d_in[21];
    const float* lnfg = (const float*)d_in[22];
    const float* lnfb = (const float*)d_in[23];
    float* out = (float*)d_out;

    float *h, *x, *o, *part, *ff, *qkv, *vt, *sc, *enc, *wot, *bos, *wqkv, *bqkv;
    float *w1c, *w2c, *skwc, *wtec;
    cudaGetSymbolAddress((void**)&h,    g_h);
    cudaGetSymbolAddress((void**)&x,    g_x);
    cudaGetSymbolAddress((void**)&o,    g_o);
    cudaGetSymbolAddress((void**)&part, g_part);
    cudaGetSymbolAddress((void**)&ff,   g_ff);
    cudaGetSymbolAddress((void**)&qkv,  g_qkv);
    cudaGetSymbolAddress((void**)&vt,   g_vt);
    cudaGetSymbolAddress((void**)&sc,   g_sc);
    cudaGetSymbolAddress((void**)&enc,  g_enc);
    cudaGetSymbolAddress((void**)&wot,  g_wot);
    cudaGetSymbolAddress((void**)&bos,  g_bos);
    cudaGetSymbolAddress((void**)&wqkv, g_wqkv);
    cudaGetSymbolAddress((void**)&bqkv, g_bqkv);
    cudaGetSymbolAddress((void**)&w1c,  g_w1c);
    cudaGetSymbolAddress((void**)&w2c,  g_w2c);
    cudaGetSymbolAddress((void**)&skwc, g_skwc);
    cudaGetSymbolAddress((void**)&wtec, g_wtec);

    cudaFuncSetAttribute(gemm_cp<0, true,  false, false, false>, cudaFuncAttributeMaxDynamicSharedMemorySize, GEMM_SMEM_BYTES);
    cudaFuncSetAttribute(gemm_cp<2, true,  false, false, true >, cudaFuncAttributeMaxDynamicSharedMemorySize, GEMM_SMEM_BYTES);
    cudaFuncSetAttribute(gemm_cp<0, false, false, false, false>, cudaFuncAttributeMaxDynamicSharedMemorySize, GEMM_SMEM_BYTES);
    cudaFuncSetAttribute(gemm_sk<false>, cudaFuncAttributeMaxDynamicSharedMemorySize, GEMM_SMEM_BYTES);
    cudaFuncSetAttribute(gemm_sk<true >, cudaFuncAttributeMaxDynamicSharedMemorySize, GEMM_SMEM_BYTES);
    cudaFuncSetAttribute(attn_scores_tc, cudaFuncAttributeMaxDynamicSharedMemorySize, SC_SMEM);

    dim3 gQKV(3 * DMODEL / 128, BT / 128);
    dim3 gSK(DMODEL / 128, BT / 128, 2);
    dim3 gF(FINNER / 128, BT / 128);
    dim3 gV(VOCAB / 128, BT / 128);
    int nAdd = (BT * DMODEL / 4 + 255) / 256;

    // keep gemm_cp (QKV, layer 0) as launch #4 for ncu visibility
    prep_wqkvb<<<(int)(((long)NLAYER * 3 * DMODEL * DMODEL + 255) / 256), 256>>>(
        Wq, Wk, Wv, bq, bk, bv, wqkv, bqkv);
    embed_k<<<(BT * DMODEL + 255) / 256, 256>>>(ids, wte, wpe, h);
    layernorm_k<<<BT, 256>>>(h, x, ln1g, ln1b);

    for (int i = 0; i < NLAYER; i++) {
        gemm_cp<0, true, false, false, false><<<gQKV, 256, GEMM_SMEM_BYTES>>>(
            x, wqkv + (long)i * 3 * DMODEL * DMODEL, bqkv + i * 3 * DMODEL, nullptr, qkv,
            BT, 3 * DMODEL, DMODEL, DMODEL, DMODEL, 3 * DMODEL);

        attn_scores_tc<<<dim3(TSEQ / 128, TSEQ / 128, BBATCH * NHEAD), 256, SC_SMEM>>>(qkv, sc);
        softmax_rows<<<dim3(TSEQ, BBATCH * NHEAD), 128>>>(sc);
        transpose_v<<<dim3(TSEQ / 32, HDIM / 32, BBATCH * NHEAD), dim3(32, 8)>>>(qkv, vt);
        attn_pv_tc<<<dim3(TSEQ / 128, BBATCH * NHEAD), 256>>>(sc, vt, o);

        if (i == 0) {
            prep_wot<<<(NLAYER * DMODEL * DMODEL + 255) / 256, 256>>>(Wo, gate, wot);
            prep_bos<<<(NLAYER * DMODEL + 255) / 256, 256>>>(bo, gate, bos);
            long n1 = (long)NLAYER * FINNER * DMODEL;
            tf32_copy<<<(int)((n1 / 4 + 255) / 256), 256>>>(w1, w1c, n1);
            tf32_copy<<<(int)((n1 / 4 + 255) / 256), 256>>>(w2, w2c, n1);
            long n2 = (long)NLAYER * DMODEL * 2 * DMODEL;
            tf32_copy<<<(int)((n2 / 4 + 255) / 256), 256>>>(skw, skwc, n2);
            long n3 = (long)VOCAB * DMODEL;
            tf32_copy<<<(int)((n3 / 4 + 255) / 256), 256>>>(wte, wtec, n3);
        }

        gemm_sk<false><<<gSK, 256, GEMM_SMEM_BYTES>>>(
            o, o + 512, wot + (long)i * DMODEL * DMODEL, part,
            512, DMODEL, DMODEL, 512);
        add_ln<true><<<BT, 256>>>(part, bos + i * DMODEL, h, x,
                                  ln2g + i * DMODEL, ln2b + i * DMODEL);
        if (i < NLAYER / 2)
            tf32_copy<<<nAdd, 256>>>(h, enc + (long)i * BT * DMODEL, (long)BT * DMODEL);

        gemm_cp<2, true, false, false, true><<<gF, 256, GEMM_SMEM_BYTES>>>(
            x, w1c + (long)i * FINNER * DMODEL, b1 + i * FINNER, nullptr, ff,
            BT, FINNER, DMODEL, DMODEL, DMODEL, FINNER);
        gemm_sk<false><<<gSK, 256, GEMM_SMEM_BYTES>>>(
            ff, ff + 2048, w2c + (long)i * DMODEL * FINNER, part,
            2048, FINNER, FINNER, 2048);

        if (i < NLAYER / 2) {
            add_ln<true><<<BT, 256>>>(part, b2 + i * DMODEL, h, x,
                                      ln1g + (i + 1) * DMODEL, ln1b + (i + 1) * DMODEL);
        } else {
            add2_k<<<nAdd, 256>>>(part, b2 + i * DMODEL, h);
            int el = NLAYER - i - 1;
            const float* sw = skwc + (long)i * DMODEL * 2 * DMODEL;
            gemm_sk<true><<<gSK, 256, GEMM_SMEM_BYTES>>>(
                h, enc + (long)el * BT * DMODEL, sw, part,
                DMODEL, DMODEL, 2 * DMODEL, DMODEL);
            if (i + 1 < NLAYER) {
                add_ln<false><<<BT, 256>>>(part, skb + i * DMODEL, h, x,
                                           ln1g + (i + 1) * DMODEL, ln1b + (i + 1) * DMODEL);
            } else {
                add_ln<false><<<BT, 256>>>(part, skb + i * DMODEL, h, x, lnfg, lnfb);
            }
        }
    }

    gemm_cp<0, false, false, false, false><<<gV, 256, GEMM_SMEM_BYTES>>>(
        x, wtec, nullptr, nullptr, out, BT, VOCAB, DMODEL, DMODEL, DMODEL, VOCAB);
}

// round 15
// speedup vs baseline: 1.0797x; 1.0478x over previous
#include <cuda_runtime.h>
#include <cuda_bf16.h>
#include <math.h>
#include <stdint.h>

// Model dims
#define BBATCH 4
#define TSEQ   512
#define BT     2048
#define DMODEL 1024
#define NHEAD  16
#define HDIM   64
#define FINNER 4096
#define VOCAB  32000
#define NLAYER 8

typedef __nv_bfloat16 bf16;

// ---------------- scratch ----------------
__device__ float g_h   [BT * DMODEL];
__device__ float g_x   [BT * DMODEL];
__device__ float g_o   [BT * DMODEL];
__device__ float g_part[2 * BT * DMODEL];
__device__ float g_ff  [BT * FINNER];
__device__ float g_qkv [BT * 3 * DMODEL];
__device__ float g_vt  [(size_t)BBATCH * NHEAD * HDIM * TSEQ];
__device__ float g_sc  [(size_t)BBATCH * NHEAD * TSEQ * TSEQ];
__device__ float g_enc [4 * BT * DMODEL];
__device__ float g_wot [NLAYER * DMODEL * DMODEL];
__device__ float g_bos [NLAYER * DMODEL];
__device__ float g_wqkv[(size_t)NLAYER * 3 * DMODEL * DMODEL];
__device__ float g_bqkv[NLAYER * 3 * DMODEL];
__device__ float g_w1c [(size_t)NLAYER * FINNER * DMODEL];
__device__ float g_w2c [(size_t)NLAYER * DMODEL * FINNER];
__device__ float g_skwc[(size_t)NLAYER * DMODEL * 2 * DMODEL];
__device__ float g_wtec[(size_t)VOCAB * DMODEL];

// ---------------- helpers ----------------
__device__ __forceinline__ unsigned f2tf(float x) {
    unsigned r; asm("cvt.rna.tf32.f32 %0, %1;" : "=r"(r) : "f"(x)); return r;
}
__device__ __forceinline__ float tfr(float x) { return __uint_as_float(f2tf(x)); }
__device__ __forceinline__ uint32_t s2u(const void* p) {
    uint32_t a;
    asm("{ .reg .u64 t; cvta.to.shared.u64 t, %1; cvt.u32.u64 %0, t; }" : "=r"(a) : "l"(p));
    return a;
}
#define CP_ASYNC16(dst, src) \
    asm volatile("cp.async.cg.shared.global [%0], [%1], 16;" :: "r"(dst), "l"(src))
#define CP_COMMIT() asm volatile("cp.async.commit_group;")
#define CP_WAIT0()  asm volatile("cp.async.wait_group 0;")
#define CP_WAIT1()  asm volatile("cp.async.wait_group 1;")

__device__ __forceinline__ void ldsm4(uint32_t& r0, uint32_t& r1, uint32_t& r2,
                                      uint32_t& r3, uint32_t addr) {
    asm volatile("ldmatrix.sync.aligned.m8n8.x4.shared.b16 {%0,%1,%2,%3}, [%4];"
                 : "=r"(r0), "=r"(r1), "=r"(r2), "=r"(r3) : "r"(addr));
}
__device__ __forceinline__ void mma_tf32(float c[4], unsigned a0, unsigned a1,
                                         unsigned a2, unsigned a3,
                                         unsigned b0, unsigned b1) {
    asm volatile(
        "mma.sync.aligned.m16n8k8.row.col.f32.tf32.tf32.f32 "
        "{%0,%1,%2,%3}, {%4,%5,%6,%7}, {%8,%9}, {%0,%1,%2,%3};"
        : "+f"(c[0]), "+f"(c[1]), "+f"(c[2]), "+f"(c[3])
        : "r"(a0), "r"(a1), "r"(a2), "r"(a3), "r"(b0), "r"(b1));
}
__device__ __forceinline__ void mma_bf16x(float c[4], unsigned a0, unsigned a1,
                                          unsigned a2, unsigned a3,
                                          unsigned b0, unsigned b1) {
    asm volatile(
        "mma.sync.aligned.m16n8k16.row.col.f32.bf16.bf16.f32 "
        "{%0,%1,%2,%3}, {%4,%5,%6,%7}, {%8,%9}, {%0,%1,%2,%3};"
        : "+f"(c[0]), "+f"(c[1]), "+f"(c[2]), "+f"(c[3])
        : "r"(a0), "r"(a1), "r"(a2), "r"(a3), "r"(b0), "r"(b1));
}
__device__ __forceinline__ void split8(float4 v0, float4 v1, uint4& hi, uint4& lo) {
    float f[8] = {v0.x, v0.y, v0.z, v0.w, v1.x, v1.y, v1.z, v1.w};
    uint32_t hs[8], ls[8];
    #pragma unroll
    for (int i = 0; i < 8; i++) {
        bf16 h = __float2bfloat16(f[i]);
        bf16 l = __float2bfloat16(f[i] - __bfloat162float(h));
        hs[i] = *(unsigned short*)&h;
        ls[i] = *(unsigned short*)&l;
    }
    hi = make_uint4(hs[0] | (hs[1] << 16), hs[2] | (hs[3] << 16),
                    hs[4] | (hs[5] << 16), hs[6] | (hs[7] << 16));
    lo = make_uint4(ls[0] | (ls[1] << 16), ls[2] | (ls[3] << 16),
                    ls[4] | (ls[5] << 16), ls[6] | (ls[7] << 16));
}

// ---------------- prep kernels ----------------
__global__ void tf32_copy(const float* __restrict__ in, float* __restrict__ out, long n) {
    long i = ((long)blockIdx.x * 256 + threadIdx.x) * 4;
    if (i >= n) return;
    float4 v = *(const float4*)(in + i);
    v.x = tfr(v.x); v.y = tfr(v.y); v.z = tfr(v.z); v.w = tfr(v.w);
    *(float4*)(out + i) = v;
}

__global__ void prep_wqkvb(const float* __restrict__ Wq, const float* __restrict__ Wk,
                           const float* __restrict__ Wv,
                           const float* __restrict__ bq, const float* __restrict__ bk,
                           const float* __restrict__ bv,
                           float* __restrict__ W, float* __restrict__ bias) {
    long idx = (long)blockIdx.x * 256 + threadIdx.x;
    if (idx >= (long)NLAYER * 3 * DMODEL * DMODEL) return;
    int l = (int)(idx / (3L * DMODEL * DMODEL));
    long rem = idx - (long)l * 3 * DMODEL * DMODEL;
    int r = (int)(rem >> 10), d = (int)(rem & 1023);
    int sel = r >> 10, rn = r & 1023;
    const float* src = sel == 0 ? Wq : (sel == 1 ? Wk : Wv);
    W[idx] = tfr(src[((long)l * DMODEL + rn) * DMODEL + d]);
    if (idx < NLAYER * 3 * DMODEL) {
        int lb = (int)(idx / (3 * DMODEL)), rb = (int)(idx % (3 * DMODEL));
        int selb = rb >> 10, rnb = rb & 1023;
        const float* b = selb == 0 ? bq : (selb == 1 ? bk : bv);
        bias[idx] = b[lb * DMODEL + rnb];
    }
}

__global__ void prep_wot(const float* __restrict__ Wo, const float* __restrict__ gate,
                         float* __restrict__ wot) {
    long idx = (long)blockIdx.x * 256 + threadIdx.x;
    if (idx >= (long)NLAYER * DMODEL * DMODEL) return;
    int l = (int)(idx >> 20);
    int d = (int)((idx >> 10) & 1023);
    int c = (int)(idx & 1023);
    int n = c >> 6, hh = c & 63;
    wot[idx] = tfr(Wo[((long)(l * NHEAD + n)) * (DMODEL * HDIM) + (long)d * HDIM + hh]
                   * gate[l * NHEAD + n]);
}

__global__ void prep_bos(const float* __restrict__ bo, const float* __restrict__ gate,
                         float* __restrict__ bos) {
    int idx = blockIdx.x * 256 + threadIdx.x;
    if (idx >= NLAYER * DMODEL) return;
    int l = idx >> 10, d = idx & 1023;
    float s = 0.f;
    for (int n = 0; n < NHEAD; n++)
        s += gate[l * NHEAD + n] * bo[(long)(l * NHEAD + n) * DMODEL + d];
    bos[idx] = s;
}

__global__ void embed_k(const int* __restrict__ ids, const float* __restrict__ wte,
                        const float* __restrict__ wpe, float* __restrict__ h) {
    long idx = (long)blockIdx.x * 256 + threadIdx.x;
    if (idx >= (long)BT * DMODEL) return;
    int bt = (int)(idx >> 10), d = (int)(idx & 1023);
    int t = bt & (TSEQ - 1);
    h[idx] = wte[(long)ids[bt] * DMODEL + d] + wpe[(long)t * DMODEL + d];
}

// ---------------- layernorm (layer-0 entry only) ----------------
__global__ void layernorm_k(const float* __restrict__ in, float* __restrict__ out,
                            const float* __restrict__ g, const float* __restrict__ b) {
    int row = blockIdx.x;
    const float* x = in + (long)row * DMODEL;
    float* y = out + (long)row * DMODEL;
    __shared__ float red[256];
    int tid = threadIdx.x;
    float s = 0.f;
    for (int i = tid; i < DMODEL; i += 256) s += x[i];
    red[tid] = s; __syncthreads();
    for (int o = 128; o > 0; o >>= 1) { if (tid < o) red[tid] += red[tid + o]; __syncthreads(); }
    float mean = red[0] * (1.0f / DMODEL);
    __syncthreads();
    float v = 0.f;
    for (int i = tid; i < DMODEL; i += 256) { float d = x[i] - mean; v += d * d; }
    red[tid] = v; __syncthreads();
    for (int o = 128; o > 0; o >>= 1) { if (tid < o) red[tid] += red[tid + o]; __syncthreads(); }
    float inv = rsqrtf(red[0] * (1.0f / DMODEL) + 1e-5f);
    for (int i = tid; i < DMODEL; i += 256)
        y[i] = tfr((x[i] - mean) * inv * g[i] + b[i]);
}

// ---------------- fused: h = (ADDH? h : 0) + p0 + p1 + bias;  x = LN(h) ------
template<bool ADDH>
__global__ void add_ln(const float* __restrict__ part, const float* __restrict__ bias,
                       float* __restrict__ h, float* __restrict__ x,
                       const float* __restrict__ g, const float* __restrict__ b) {
    int row = blockIdx.x;
    int tid = threadIdx.x;
    __shared__ float buf[DMODEL];
    __shared__ float red[256];
    const float* p0 = part + (long)row * DMODEL;
    const float* p1 = part + (long)BT * DMODEL + (long)row * DMODEL;
    float* hp = h + (long)row * DMODEL;
    float* xp = x + (long)row * DMODEL;
    float s = 0.f;
    for (int i = tid; i < DMODEL; i += 256) {
        float v = p0[i] + p1[i] + bias[i];
        if (ADDH) v += hp[i];
        buf[i] = v;
        hp[i] = v;
        s += v;
    }
    red[tid] = s; __syncthreads();
    for (int o = 128; o > 0; o >>= 1) { if (tid < o) red[tid] += red[tid + o]; __syncthreads(); }
    float mean = red[0] * (1.0f / DMODEL);
    __syncthreads();
    float v2 = 0.f;
    for (int i = tid; i < DMODEL; i += 256) { float d = buf[i] - mean; v2 += d * d; }
    red[tid] = v2; __syncthreads();
    for (int o = 128; o > 0; o >>= 1) { if (tid < o) red[tid] += red[tid + o]; __syncthreads(); }
    float inv = rsqrtf(red[0] * (1.0f / DMODEL) + 1e-5f);
    for (int i = tid; i < DMODEL; i += 256)
        xp[i] = tfr((buf[i] - mean) * inv * g[i] + b[i]);
}

__global__ void add2_k(const float* __restrict__ part, const float* __restrict__ bias,
                       float* __restrict__ out) {
    long i = ((long)blockIdx.x * 256 + threadIdx.x) * 4;
    if (i >= (long)BT * DMODEL) return;
    int n = (int)(i & (DMODEL - 1));
    float4 p0 = *(const float4*)(part + i);
    float4 p1 = *(const float4*)(part + (long)BT * DMODEL + i);
    float4 b4 = *(const float4*)(bias + n);
    float4 r4 = *(const float4*)(out + i);
    float4 v;
    v.x = p0.x + p1.x + b4.x + r4.x;
    v.y = p0.y + p1.y + b4.y + r4.y;
    v.z = p0.z + p1.z + b4.z + r4.z;
    v.w = p0.w + p1.w + b4.w + r4.w;
    *(float4*)(out + i) = v;
}

// ---------------- tf32 GEMM, 2-stage cp.async, ldmatrix fragments ----------
#define SMEM_STRIDE 36
#define TILE_U (128 * SMEM_STRIDE)
#define GEMM_SMEM_BYTES (4 * TILE_U * 4)

// one 32-K chunk; fragments via ldmatrix.x4 (b16 view of tf32 data)
template<bool CVTA>
__device__ __forceinline__ void mma_chunk(
    uint32_t Abase, uint32_t Bbase,
    uint32_t offA0, uint32_t offA1,
    uint32_t offB0, uint32_t offB1, uint32_t offB2, uint32_t offB3,
    float acc[2][8][4]) {
    #pragma unroll
    for (int ks = 0; ks < 4; ks++) {
        uint32_t ko = (uint32_t)ks * 32;   // 8 floats along k
        uint32_t a[2][4];
        ldsm4(a[0][0], a[0][1], a[0][2], a[0][3], Abase + offA0 + ko);
        ldsm4(a[1][0], a[1][1], a[1][2], a[1][3], Abase + offA1 + ko);
        if (CVTA) {
            #pragma unroll
            for (int i = 0; i < 2; i++)
                #pragma unroll
                for (int q = 0; q < 4; q++)
                    a[i][q] = f2tf(__uint_as_float(a[i][q]));
        }
        uint32_t offB[4] = {offB0, offB1, offB2, offB3};
        #pragma unroll
        for (int jj = 0; jj < 4; jj++) {
            uint32_t b0, b1, b2, b3;
            ldsm4(b0, b1, b2, b3, Bbase + offB[jj] + ko);
            mma_tf32(acc[0][2 * jj],     a[0][0], a[0][1], a[0][2], a[0][3], b0, b1);
            mma_tf32(acc[1][2 * jj],     a[1][0], a[1][1], a[1][2], a[1][3], b0, b1);
            mma_tf32(acc[0][2 * jj + 1], a[0][0], a[0][1], a[0][2], a[0][3], b2, b3);
            mma_tf32(acc[1][2 * jj + 1], a[1][0], a[1][1], a[1][2], a[1][3], b2, b3);
        }
    }
}

template<int EPI, bool BIAS, bool RES, bool CVTA, bool ROUND>
__global__ __launch_bounds__(256, 2) void gemm_cp(
    const float* __restrict__ A, const float* __restrict__ Bm,
    const float* __restrict__ bias, const float* __restrict__ res,
    float* __restrict__ C, int M, int N, int K, int lda, int ldb, int ldc) {
    extern __shared__ float sm[];
    float* As = sm;
    float* Bs = sm + 2 * TILE_U;
    const uint32_t AsU = s2u(As), BsU = s2u(Bs);

    int tid = threadIdx.x, lane = tid & 31, warp = tid >> 5;
    int wm = warp & 3, wn = warp >> 2;
    int m0 = blockIdx.y * 128, n0 = blockIdx.x * 128;
    const float* Ag = A + (long)m0 * lda;
    const float* Bg = Bm + (long)n0 * ldb;

    const float* Asrc[4]; const float* Bsrc[4];
    uint32_t Adst[4], Bdst[4];
    #pragma unroll
    for (int i = 0; i < 4; i++) {
        int idx = tid + i * 256;
        int r = idx >> 3, c = (idx & 7) * 4;
        Asrc[i] = Ag + (long)r * lda + c;
        Bsrc[i] = Bg + (long)r * ldb + c;
        Adst[i] = AsU + (uint32_t)(r * SMEM_STRIDE + c) * 4;
        Bdst[i] = BsU + (uint32_t)(r * SMEM_STRIDE + c) * 4;
    }

    float acc[2][8][4];
    #pragma unroll
    for (int i = 0; i < 2; i++)
        #pragma unroll
        for (int j = 0; j < 8; j++)
            #pragma unroll
            for (int q = 0; q < 4; q++) acc[i][j][q] = 0.f;

    // ldmatrix per-thread row addresses (byte offsets within a stage)
    int mat = lane >> 3, r8 = lane & 7;
    uint32_t offA0 = (uint32_t)(((wm * 32 + (mat & 1) * 8 + r8) * SMEM_STRIDE
                                 + (mat >> 1) * 4) * 4);
    uint32_t offA1 = offA0 + (uint32_t)(16 * SMEM_STRIDE * 4);
    uint32_t offB[4];
    #pragma unroll
    for (int jj = 0; jj < 4; jj++)
        offB[jj] = (uint32_t)(((wn * 64 + jj * 16 + (mat >> 1) * 8 + r8) * SMEM_STRIDE
                               + (mat & 1) * 4) * 4);

    #pragma unroll
    for (int i = 0; i < 4; i++) {
        CP_ASYNC16(Adst[i], Asrc[i]);
        CP_ASYNC16(Bdst[i], Bsrc[i]);
    }
    CP_COMMIT();

    int p = 0;
    for (int k0 = 0; k0 < K; k0 += 32) {
        if (k0 + 32 < K) {
            uint32_t po = (uint32_t)((p ^ 1) * TILE_U) * 4;
            #pragma unroll
            for (int i = 0; i < 4; i++) {
                CP_ASYNC16(Adst[i] + po, Asrc[i] + k0 + 32);
                CP_ASYNC16(Bdst[i] + po, Bsrc[i] + k0 + 32);
            }
            CP_COMMIT();
            CP_WAIT1();
        } else {
            CP_WAIT0();
        }
        __syncthreads();
        uint32_t so = (uint32_t)(p * TILE_U) * 4;
        mma_chunk<CVTA>(AsU + so, BsU + so, offA0, offA1,
                        offB[0], offB[1], offB[2], offB[3], acc);
        __syncthreads();
        p ^= 1;
    }

    #pragma unroll
    for (int i = 0; i < 2; i++) {
        int m = m0 + wm * 32 + i * 16 + (lane >> 2);
        #pragma unroll
        for (int j = 0; j < 8; j++) {
            int n = n0 + wn * 64 + j * 8 + (lane & 3) * 2;
            #pragma unroll
            for (int q = 0; q < 2; q++) {
                int mm = m + q * 8;
                float v0 = acc[i][j][q * 2 + 0];
                float v1 = acc[i][j][q * 2 + 1];
                if (BIAS) { v0 += bias[n]; v1 += bias[n + 1]; }
                if (RES)  { v0 += res[(long)mm * ldc + n]; v1 += res[(long)mm * ldc + n + 1]; }
                if (EPI == 2) {
                    v0 = 0.5f * v0 * (1.0f + erff(v0 * 0.70710678118654752f));
                    v1 = 0.5f * v1 * (1.0f + erff(v1 * 0.70710678118654752f));
                }
                if (ROUND) { v0 = tfr(v0); v1 = tfr(v1); }
                C[(long)mm * ldc + n]     = v0;
                C[(long)mm * ldc + n + 1] = v1;
            }
        }
    }
}

// ---------------- split-K / dual-source tf32 GEMM ----------------
template<bool CVTA>
__global__ __launch_bounds__(256, 2) void gemm_sk(
    const float* __restrict__ A0, const float* __restrict__ A1,
    const float* __restrict__ Bm, float* __restrict__ part,
    int K2, int lda, int ldb, int boff) {
    extern __shared__ float sm[];
    float* As = sm;
    float* Bs = sm + 2 * TILE_U;
    const uint32_t AsU = s2u(As), BsU = s2u(Bs);

    int tid = threadIdx.x, lane = tid & 31, warp = tid >> 5;
    int wm = warp & 3, wn = warp >> 2;
    int m0 = blockIdx.y * 128, n0 = blockIdx.x * 128;
    int z = blockIdx.z;
    const float* Ag = (z ? A1 : A0) + (long)m0 * lda;
    const float* Bg = Bm + (long)n0 * ldb + (long)z * boff;
    float* C = part + (long)z * BT * DMODEL;

    const float* Asrc[4]; const float* Bsrc[4];
    uint32_t Adst[4], Bdst[4];
    #pragma unroll
    for (int i = 0; i < 4; i++) {
        int idx = tid + i * 256;
        int r = idx >> 3, c = (idx & 7) * 4;
        Asrc[i] = Ag + (long)r * lda + c;
        Bsrc[i] = Bg + (long)r * ldb + c;
        Adst[i] = AsU + (uint32_t)(r * SMEM_STRIDE + c) * 4;
        Bdst[i] = BsU + (uint32_t)(r * SMEM_STRIDE + c) * 4;
    }

    float acc[2][8][4];
    #pragma unroll
    for (int i = 0; i < 2; i++)
        #pragma unroll
        for (int j = 0; j < 8; j++)
            #pragma unroll
            for (int q = 0; q < 4; q++) acc[i][j][q] = 0.f;

    int mat = lane >> 3, r8 = lane & 7;
    uint32_t offA0 = (uint32_t)(((wm * 32 + (mat & 1) * 8 + r8) * SMEM_STRIDE
                                 + (mat >> 1) * 4) * 4);
    uint32_t offA1 = offA0 + (uint32_t)(16 * SMEM_STRIDE * 4);
    uint32_t offB[4];
    #pragma unroll
    for (int jj = 0; jj < 4; jj++)
        offB[jj] = (uint32_t)(((wn * 64 + jj * 16 + (mat >> 1) * 8 + r8) * SMEM_STRIDE
                               + (mat & 1) * 4) * 4);

    #pragma unroll
    for (int i = 0; i < 4; i++) {
        CP_ASYNC16(Adst[i], Asrc[i]);
        CP_ASYNC16(Bdst[i], Bsrc[i]);
    }
    CP_COMMIT();

    int p = 0;
    for (int k0 = 0; k0 < K2; k0 += 32) {
        if (k0 + 32 < K2) {
            uint32_t po = (uint32_t)((p ^ 1) * TILE_U) * 4;
            #pragma unroll
            for (int i = 0; i < 4; i++) {
                CP_ASYNC16(Adst[i] + po, Asrc[i] + k0 + 32);
                CP_ASYNC16(Bdst[i] + po, Bsrc[i] + k0 + 32);
            }
            CP_COMMIT();
            CP_WAIT1();
        } else {
            CP_WAIT0();
        }
        __syncthreads();
        uint32_t so = (uint32_t)(p * TILE_U) * 4;
        mma_chunk<CVTA>(AsU + so, BsU + so, offA0, offA1,
                        offB[0], offB[1], offB[2], offB[3], acc);
        __syncthreads();
        p ^= 1;
    }

    #pragma unroll
    for (int i = 0; i < 2; i++) {
        int m = m0 + wm * 32 + i * 16 + (lane >> 2);
        #pragma unroll
        for (int j = 0; j < 8; j++) {
            int n = n0 + wn * 64 + j * 8 + (lane & 3) * 2;
            #pragma unroll
            for (int q = 0; q < 2; q++) {
                int mm = m + q * 8;
                C[(long)mm * DMODEL + n]     = acc[i][j][q * 2 + 0];
                C[(long)mm * DMODEL + n + 1] = acc[i][j][q * 2 + 1];
            }
        }
    }
}

// ---------------- attention scores: bf16 3-pass mma ----------------
#define SC_STR 36
#define SC_PLANE (128 * SC_STR)
#define SC_SMEM (4 * SC_PLANE * 4)

__global__ __launch_bounds__(256) void attn_scores_tc(
    const float* __restrict__ qkv, float* __restrict__ S) {
    int bh = blockIdx.z;
    int b = bh >> 4, n = bh & 15;
    int s0 = blockIdx.x * 128, t0 = blockIdx.y * 128;
    if (s0 > t0) return;
    extern __shared__ uint32_t smq[];
    uint32_t* Qh = smq;
    uint32_t* Ql = smq + SC_PLANE;
    uint32_t* Kh = smq + 2 * SC_PLANE;
    uint32_t* Kl = smq + 3 * SC_PLANE;
    int tid = threadIdx.x, lane = tid & 31, warp = tid >> 5;
    const float* Qp = qkv + ((long)(b * TSEQ + t0)) * (3 * DMODEL) + n * HDIM;
    const float* Kp = qkv + ((long)(b * TSEQ + s0)) * (3 * DMODEL) + DMODEL + n * HDIM;
    for (int g = tid; g < 2048; g += 256) {
        int isK = g >= 1024;
        int gg = g & 1023;
        int r = gg >> 3, c8 = (gg & 7) * 8;
        const float* src = (isK ? Kp : Qp) + (long)r * (3 * DMODEL) + c8;
        float4 v0 = *(const float4*)src;
        float4 v1 = *(const float4*)(src + 4);
        uint4 hi, lo;
        split8(v0, v1, hi, lo);
        int off = r * SC_STR + c8 / 2;
        *(uint4*)((isK ? Kh : Qh) + off) = hi;
        *(uint4*)((isK ? Kl : Ql) + off) = lo;
    }
    __syncthreads();

    int wm = warp & 3, wn = warp >> 2;
    int mrow = wm * 32 + (lane >> 2);
    int nrow = wn * 64 + (lane >> 2);
    int kt = lane & 3;
    float acc[2][8][4];
    #pragma unroll
    for (int i = 0; i < 2; i++)
        #pragma unroll
        for (int j = 0; j < 8; j++)
            #pragma unroll
            for (int q = 0; q < 4; q++) acc[i][j][q] = 0.f;

    const uint32_t* Ap[3] = {Qh, Qh, Ql};
    const uint32_t* Bp[3] = {Kh, Kl, Kh};
    #pragma unroll
    for (int p = 0; p < 3; p++) {
        #pragma unroll
        for (int ks = 0; ks < 4; ks++) {
            int kk = ks * 8 + kt;
            unsigned af[2][4];
            #pragma unroll
            for (int i = 0; i < 2; i++) {
                const uint32_t* base = Ap[p] + (mrow + i * 16) * SC_STR;
                af[i][0] = base[kk];
                af[i][1] = base[8 * SC_STR + kk];
                af[i][2] = base[kk + 4];
                af[i][3] = base[8 * SC_STR + kk + 4];
            }
            #pragma unroll
            for (int j = 0; j < 8; j++) {
                const uint32_t* bb = Bp[p] + (nrow + j * 8) * SC_STR;
                unsigned b0 = bb[kk], b1 = bb[kk + 4];
                #pragma unroll
                for (int i = 0; i < 2; i++)
                    mma_bf16x(acc[i][j], af[i][0], af[i][1], af[i][2], af[i][3], b0, b1);
            }
        }
    }
    float* Sp = S + ((long)bh * TSEQ + t0) * TSEQ + s0;
    #pragma unroll
    for (int i = 0; i < 2; i++) {
        int rr = wm * 32 + i * 16 + (lane >> 2);
        #pragma unroll
        for (int j = 0; j < 8; j++) {
            int cc = wn * 64 + j * 8 + (lane & 3) * 2;
            #pragma unroll
            for (int q = 0; q < 2; q++) {
                Sp[(long)(rr + q * 8) * TSEQ + cc]     = acc[i][j][q * 2 + 0] * 0.125f;
                Sp[(long)(rr + q * 8) * TSEQ + cc + 1] = acc[i][j][q * 2 + 1] * 0.125f;
            }
        }
    }
}

// ---------------- softmax ----------------
__global__ void softmax_rows(float* __restrict__ S) {
    int t = blockIdx.x, bh = blockIdx.y;
    float* row = S + ((long)bh * TSEQ + t) * TSEQ;
    int len = t + 1;
    __shared__ float red[128];
    int tid = threadIdx.x;
    float mx = -1e30f;
    for (int s = tid; s < len; s += 128) mx = fmaxf(mx, row[s]);
    red[tid] = mx; __syncthreads();
    for (int o = 64; o > 0; o >>= 1) { if (tid < o) red[tid] = fmaxf(red[tid], red[tid + o]); __syncthreads(); }
    mx = red[0]; __syncthreads();
    float sum = 0.f;
    for (int s = tid; s < len; s += 128) { float e = __expf(row[s] - mx); row[s] = e; sum += e; }
    red[tid] = sum; __syncthreads();
    for (int o = 64; o > 0; o >>= 1) { if (tid < o) red[tid] += red[tid + o]; __syncthreads(); }
    float inv = 1.0f / red[0];
    for (int s = tid; s < len; s += 128) row[s] *= inv;
    for (int s = len + tid; s < TSEQ; s += 128) row[s] = 0.0f;
}

// ---------------- V transpose ----------------
__global__ void transpose_v(const float* __restrict__ qkv, float* __restrict__ Vt) {
    int bh = blockIdx.z;
    int b = bh >> 4, n = bh & 15;
    int tt = blockIdx.x * 32, dd = blockIdx.y * 32;
    __shared__ float tile[32][33];
    int tx = threadIdx.x, ty = threadIdx.y;
    #pragma unroll
    for (int i = 0; i < 4; i++) {
        int t = tt + ty + i * 8;
        tile[ty + i * 8][tx] =
            qkv[((long)(b * TSEQ + t)) * (3 * DMODEL) + 2 * DMODEL + n * HDIM + dd + tx];
    }
    __syncthreads();
    #pragma unroll
    for (int i = 0; i < 4; i++) {
        int d = dd + ty + i * 8;
        Vt[((long)bh * HDIM + d) * TSEQ + tt + tx] = tile[tx][ty + i * 8];
    }
}

// ---------------- attention PV: bf16 3-pass mma (tf32-rounded output) -------
#define PV_STR 20

__global__ __launch_bounds__(256) void attn_pv_tc(
    const float* __restrict__ P, const float* __restrict__ Vt, float* __restrict__ O) {
    int bh = blockIdx.y;
    int b = bh >> 4, n = bh & 15;
    int t0 = blockIdx.x * 128;
    __shared__ uint32_t Ph[128 * PV_STR], Pl[128 * PV_STR];
    __shared__ uint32_t Vh[64 * PV_STR],  Vl[64 * PV_STR];
    int tid = threadIdx.x, lane = tid & 31, warp = tid >> 5;
    int wm = warp & 3, wn = warp >> 2;
    int mrow = wm * 32 + (lane >> 2);
    int nrow = wn * 32 + (lane >> 2);
    int kt = lane & 3;
    const float* Pp = P + ((long)bh * TSEQ + t0) * TSEQ;
    const float* Vp = Vt + (long)bh * HDIM * TSEQ;

    float acc[2][4][4];
    #pragma unroll
    for (int i = 0; i < 2; i++)
        #pragma unroll
        for (int j = 0; j < 4; j++)
            #pragma unroll
            for (int q = 0; q < 4; q++) acc[i][j][q] = 0.f;

    int kmax = t0 + 128;
    for (int k0 = 0; k0 < kmax; k0 += 32) {
        for (int g = tid; g < 768; g += 256) {
            const float* src; uint32_t *dh, *dl;
            if (g < 512) {
                int r = g >> 2, c8 = (g & 3) * 8;
                src = Pp + (long)r * TSEQ + k0 + c8;
                dh = Ph + r * PV_STR + c8 / 2; dl = Pl + r * PV_STR + c8 / 2;
            } else {
                int v = g - 512;
                int r = v >> 2, c8 = (v & 3) * 8;
                src = Vp + (long)r * TSEQ + k0 + c8;
                dh = Vh + r * PV_STR + c8 / 2; dl = Vl + r * PV_STR + c8 / 2;
            }
            float4 v0 = *(const float4*)src;
            float4 v1 = *(const float4*)(src + 4);
            uint4 hi, lo;
            split8(v0, v1, hi, lo);
            *(uint4*)dh = hi;
            *(uint4*)dl = lo;
        }
        __syncthreads();
        const uint32_t* Ap[3] = {Ph, Ph, Pl};
        const uint32_t* Bp[3] = {Vh, Vl, Vh};
        #pragma unroll
        for (int p = 0; p < 3; p++) {
            #pragma unroll
            for (int ks = 0; ks < 2; ks++) {
                int kk = ks * 8 + kt;
                unsigned af[2][4];
                #pragma unroll
                for (int i = 0; i < 2; i++) {
                    const uint32_t* base = Ap[p] + (mrow + i * 16) * PV_STR;
                    af[i][0] = base[kk];
                    af[i][1] = base[8 * PV_STR + kk];
                    af[i][2] = base[kk + 4];
                    af[i][3] = base[8 * PV_STR + kk + 4];
                }
                #pragma unroll
                for (int j = 0; j < 4; j++) {
                    const uint32_t* bb = Bp[p] + (nrow + j * 8) * PV_STR;
                    unsigned b0 = bb[kk], b1 = bb[kk + 4];
                    #pragma unroll
                    for (int i = 0; i < 2; i++)
                        mma_bf16x(acc[i][j], af[i][0], af[i][1], af[i][2], af[i][3], b0, b1);
                }
            }
        }
        __syncthreads();
    }
    #pragma unroll
    for (int i = 0; i < 2; i++) {
        int rr = t0 + wm * 32 + i * 16 + (lane >> 2);
        #pragma unroll
        for (int j = 0; j < 4; j++) {
            int cc = n * HDIM + wn * 32 + j * 8 + (lane & 3) * 2;
            #pragma unroll
            for (int q = 0; q < 2; q++) {
                O[(long)(b * TSEQ + rr + q * 8) * DMODEL + cc]     = tfr(acc[i][j][q * 2 + 0]);
                O[(long)(b * TSEQ + rr + q * 8) * DMODEL + cc + 1] = tfr(acc[i][j][q * 2 + 1]);
            }
        }
    }
}

// ---------------- orchestration ----------------
extern "C" void kernel_launch(void* const* d_in, const int* in_sizes, int n_in,
                              void* d_out, int out_size) {
    const int*   ids  = (const int*)d_in[0];
    const float* wte  = (const float*)d_in[1];
    const float* wpe  = (const float*)d_in[2];
    const float* Wq   = (const float*)d_in[3];
    const float* bq   = (const float*)d_in[4];
    const float* Wk   = (const float*)d_in[5];
    const float* bk   = (const float*)d_in[6];
    const float* Wv   = (const float*)d_in[7];
    const float* bv   = (const float*)d_in[8];
    const float* Wo   = (const float*)d_in[9];
    const float* bo   = (const float*)d_in[10];
    const float* gate = (const float*)d_in[11];
    const float* ln1g = (const float*)d_in[12];
    const float* ln1b = (const float*)d_in[13];
    const float* ln2g = (const float*)d_in[14];
    const float* ln2b = (const float*)d_in[15];
    const float* w1   = (const float*)d_in[16];
    const float* b1   = (const float*)d_in[17];
    const float* w2   = (const float*)d_in[18];
    const float* b2   = (const float*)d_in[19];
    const float* skw  = (const float*)d_in[20];
    const float* skb  = (const float*)d_in[21];
    const float* lnfg = (const float*)d_in[22];
    const float* lnfb = (const float*)d_in[23];
    float* out = (float*)d_out;

    float *h, *x, *o, *part, *ff, *qkv, *vt, *sc, *enc, *wot, *bos, *wqkv, *bqkv;
    float *w1c, *w2c, *skwc, *wtec;
    cudaGetSymbolAddress((void**)&h,    g_h);
    cudaGetSymbolAddress((void**)&x,    g_x);
    cudaGetSymbolAddress((void**)&o,    g_o);
    cudaGetSymbolAddress((void**)&part, g_part);
    cudaGetSymbolAddress((void**)&ff,   g_ff);
    cudaGetSymbolAddress((void**)&qkv,  g_qkv);
    cudaGetSymbolAddress((void**)&vt,   g_vt);
    cudaGetSymbolAddress((void**)&sc,   g_sc);
    cudaGetSymbolAddress((void**)&enc,  g_enc);
    cudaGetSymbolAddress((void**)&wot,  g_wot);
    cudaGetSymbolAddress((void**)&bos,  g_bos);
    cudaGetSymbolAddress((void**)&wqkv, g_wqkv);
    cudaGetSymbolAddress((void**)&bqkv, g_bqkv);
    cudaGetSymbolAddress((void**)&w1c,  g_w1c);
    cudaGetSymbolAddress((void**)&w2c,  g_w2c);
    cudaGetSymbolAddress((void**)&skwc, g_skwc);
    cudaGetSymbolAddress((void**)&wtec, g_wtec);

    cudaFuncSetAttribute(gemm_cp<0, true,  false, false, false>, cudaFuncAttributeMaxDynamicSharedMemorySize, GEMM_SMEM_BYTES);
    cudaFuncSetAttribute(gemm_cp<2, true,  false, false, true >, cudaFuncAttributeMaxDynamicSharedMemorySize, GEMM_SMEM_BYTES);
    cudaFuncSetAttribute(gemm_cp<0, false, false, false, false>, cudaFuncAttributeMaxDynamicSharedMemorySize, GEMM_SMEM_BYTES);
    cudaFuncSetAttribute(gemm_sk<false>, cudaFuncAttributeMaxDynamicSharedMemorySize, GEMM_SMEM_BYTES);
    cudaFuncSetAttribute(gemm_sk<true >, cudaFuncAttributeMaxDynamicSharedMemorySize, GEMM_SMEM_BYTES);
    cudaFuncSetAttribute(attn_scores_tc, cudaFuncAttributeMaxDynamicSharedMemorySize, SC_SMEM);

    dim3 gQKV(3 * DMODEL / 128, BT / 128);
    dim3 gSK(DMODEL / 128, BT / 128, 2);
    dim3 gF(FINNER / 128, BT / 128);
    dim3 gV(VOCAB / 128, BT / 128);
    int nAdd = (BT * DMODEL / 4 + 255) / 256;

    // keep gemm_cp (QKV, layer 0) as launch #4 for ncu visibility
    prep_wqkvb<<<(int)(((long)NLAYER * 3 * DMODEL * DMODEL + 255) / 256), 256>>>(
        Wq, Wk, Wv, bq, bk, bv, wqkv, bqkv);
    embed_k<<<(BT * DMODEL + 255) / 256, 256>>>(ids, wte, wpe, h);
    layernorm_k<<<BT, 256>>>(h, x, ln1g, ln1b);

    for (int i = 0; i < NLAYER; i++) {
        gemm_cp<0, true, false, false, false><<<gQKV, 256, GEMM_SMEM_BYTES>>>(
            x, wqkv + (long)i * 3 * DMODEL * DMODEL, bqkv + i * 3 * DMODEL, nullptr, qkv,
            BT, 3 * DMODEL, DMODEL, DMODEL, DMODEL, 3 * DMODEL);

        attn_scores_tc<<<dim3(TSEQ / 128, TSEQ / 128, BBATCH * NHEAD), 256, SC_SMEM>>>(qkv, sc);
        softmax_rows<<<dim3(TSEQ, BBATCH * NHEAD), 128>>>(sc);
        transpose_v<<<dim3(TSEQ / 32, HDIM / 32, BBATCH * NHEAD), dim3(32, 8)>>>(qkv, vt);
        attn_pv_tc<<<dim3(TSEQ / 128, BBATCH * NHEAD), 256>>>(sc, vt, o);

        if (i == 0) {
            prep_wot<<<(NLAYER * DMODEL * DMODEL + 255) / 256, 256>>>(Wo, gate, wot);
            prep_bos<<<(NLAYER * DMODEL + 255) / 256, 256>>>(bo, gate, bos);
            long n1 = (long)NLAYER * FINNER * DMODEL;
            tf32_copy<<<(int)((n1 / 4 + 255) / 256), 256>>>(w1, w1c, n1);
            tf32_copy<<<(int)((n1 / 4 + 255) / 256), 256>>>(w2, w2c, n1);
            long n2 = (long)NLAYER * DMODEL * 2 * DMODEL;
            tf32_copy<<<(int)((n2 / 4 + 255) / 256), 256>>>(skw, skwc, n2);
            long n3 = (long)VOCAB * DMODEL;
            tf32_copy<<<(int)((n3 / 4 + 255) / 256), 256>>>(wte, wtec, n3);
        }

        gemm_sk<false><<<gSK, 256, GEMM_SMEM_BYTES>>>(
            o, o + 512, wot + (long)i * DMODEL * DMODEL, part,
            512, DMODEL, DMODEL, 512);
        add_ln<true><<<BT, 256>>>(part, bos + i * DMODEL, h, x,
                                  ln2g + i * DMODEL, ln2b + i * DMODEL);
        if (i < NLAYER / 2)
            tf32_copy<<<nAdd, 256>>>(h, enc + (long)i * BT * DMODEL, (long)BT * DMODEL);

        gemm_cp<2, true, false, false, true><<<gF, 256, GEMM_SMEM_BYTES>>>(
            x, w1c + (long)i * FINNER * DMODEL, b1 + i * FINNER, nullptr, ff,
            BT, FINNER, DMODEL, DMODEL, DMODEL, FINNER);
        gemm_sk<false><<<gSK, 256, GEMM_SMEM_BYTES>>>(
            ff, ff + 2048, w2c + (long)i * DMODEL * FINNER, part,
            2048, FINNER, FINNER, 2048);

        if (i < NLAYER / 2) {
            add_ln<true><<<BT, 256>>>(part, b2 + i * DMODEL, h, x,
                                      ln1g + (i + 1) * DMODEL, ln1b + (i + 1) * DMODEL);
        } else {
            add2_k<<<nAdd, 256>>>(part, b2 + i * DMODEL, h);
            int el = NLAYER - i - 1;
            const float* sw = skwc + (long)i * DMODEL * 2 * DMODEL;
            gemm_sk<true><<<gSK, 256, GEMM_SMEM_BYTES>>>(
                h, enc + (long)el * BT * DMODEL, sw, part,
                DMODEL, DMODEL, 2 * DMODEL, DMODEL);
            if (i + 1 < NLAYER) {
                add_ln<false><<<BT, 256>>>(part, skb + i * DMODEL, h, x,
                                           ln1g + (i + 1) * DMODEL, ln1b + (i + 1) * DMODEL);
            } else {
                add_ln<false><<<BT, 256>>>(part, skb + i * DMODEL, h, x, lnfg, lnfb);
            }
        }
    }

    gemm_cp<0, false, false, false, false><<<gV, 256, GEMM_SMEM_BYTES>>>(
        x, wtec, nullptr, nullptr, out, BT, VOCAB, DMODEL, DMODEL, DMODEL, VOCAB);
}

// round 16
// speedup vs baseline: 1.0926x; 1.0119x over previous
#include <cuda_runtime.h>
#include <cuda_bf16.h>
#include <math.h>
#include <stdint.h>

// Model dims
#define BBATCH 4
#define TSEQ   512
#define BT     2048
#define DMODEL 1024
#define NHEAD  16
#define HDIM   64
#define FINNER 4096
#define VOCAB  32000
#define NLAYER 8

typedef __nv_bfloat16 bf16;

// ---------------- scratch ----------------
__device__ float g_h   [BT * DMODEL];
__device__ float g_x   [BT * DMODEL];
__device__ float g_o   [BT * DMODEL];
__device__ float g_part[2 * BT * DMODEL];
__device__ float g_ff  [BT * FINNER];
__device__ float g_qkv [BT * 3 * DMODEL];
__device__ float g_vt  [(size_t)BBATCH * NHEAD * HDIM * TSEQ];
__device__ float g_sc  [(size_t)BBATCH * NHEAD * TSEQ * TSEQ];
__device__ float g_enc [4 * BT * DMODEL];
__device__ float g_wot [NLAYER * DMODEL * DMODEL];
__device__ float g_bos [NLAYER * DMODEL];
__device__ float g_wqkv[(size_t)NLAYER * 3 * DMODEL * DMODEL];
__device__ float g_bqkv[NLAYER * 3 * DMODEL];
__device__ float g_w1c [(size_t)NLAYER * FINNER * DMODEL];
__device__ float g_w2c [(size_t)NLAYER * DMODEL * FINNER];
__device__ float g_skwc[(size_t)NLAYER * DMODEL * 2 * DMODEL];
__device__ float g_wtec[(size_t)VOCAB * DMODEL];

// ---------------- helpers ----------------
__device__ __forceinline__ unsigned f2tf(float x) {
    unsigned r; asm("cvt.rna.tf32.f32 %0, %1;" : "=r"(r) : "f"(x)); return r;
}
__device__ __forceinline__ float tfr(float x) { return __uint_as_float(f2tf(x)); }
__device__ __forceinline__ uint32_t s2u(const void* p) {
    uint32_t a;
    asm("{ .reg .u64 t; cvta.to.shared.u64 t, %1; cvt.u32.u64 %0, t; }" : "=r"(a) : "l"(p));
    return a;
}
#define CP_ASYNC16(dst, src) \
    asm volatile("cp.async.cg.shared.global [%0], [%1], 16;" :: "r"(dst), "l"(src))
#define CP_COMMIT() asm volatile("cp.async.commit_group;")
#define CP_WAIT0()  asm volatile("cp.async.wait_group 0;")
#define CP_WAIT1()  asm volatile("cp.async.wait_group 1;")

__device__ __forceinline__ void ldsm4(uint32_t& r0, uint32_t& r1, uint32_t& r2,
                                      uint32_t& r3, uint32_t addr) {
    asm volatile("ldmatrix.sync.aligned.m8n8.x4.shared.b16 {%0,%1,%2,%3}, [%4];"
                 : "=r"(r0), "=r"(r1), "=r"(r2), "=r"(r3) : "r"(addr));
}
__device__ __forceinline__ void mma_tf32(float c[4], unsigned a0, unsigned a1,
                                         unsigned a2, unsigned a3,
                                         unsigned b0, unsigned b1) {
    asm volatile(
        "mma.sync.aligned.m16n8k8.row.col.f32.tf32.tf32.f32 "
        "{%0,%1,%2,%3}, {%4,%5,%6,%7}, {%8,%9}, {%0,%1,%2,%3};"
        : "+f"(c[0]), "+f"(c[1]), "+f"(c[2]), "+f"(c[3])
        : "r"(a0), "r"(a1), "r"(a2), "r"(a3), "r"(b0), "r"(b1));
}
__device__ __forceinline__ void mma_bf16x(float c[4], unsigned a0, unsigned a1,
                                          unsigned a2, unsigned a3,
                                          unsigned b0, unsigned b1) {
    asm volatile(
        "mma.sync.aligned.m16n8k16.row.col.f32.bf16.bf16.f32 "
        "{%0,%1,%2,%3}, {%4,%5,%6,%7}, {%8,%9}, {%0,%1,%2,%3};"
        : "+f"(c[0]), "+f"(c[1]), "+f"(c[2]), "+f"(c[3])
        : "r"(a0), "r"(a1), "r"(a2), "r"(a3), "r"(b0), "r"(b1));
}
__device__ __forceinline__ void split8(float4 v0, float4 v1, uint4& hi, uint4& lo) {
    float f[8] = {v0.x, v0.y, v0.z, v0.w, v1.x, v1.y, v1.z, v1.w};
    uint32_t hs[8], ls[8];
    #pragma unroll
    for (int i = 0; i < 8; i++) {
        bf16 h = __float2bfloat16(f[i]);
        bf16 l = __float2bfloat16(f[i] - __bfloat162float(h));
        hs[i] = *(unsigned short*)&h;
        ls[i] = *(unsigned short*)&l;
    }
    hi = make_uint4(hs[0] | (hs[1] << 16), hs[2] | (hs[3] << 16),
                    hs[4] | (hs[5] << 16), hs[6] | (hs[7] << 16));
    lo = make_uint4(ls[0] | (ls[1] << 16), ls[2] | (ls[3] << 16),
                    ls[4] | (ls[5] << 16), ls[6] | (ls[7] << 16));
}

// ---------------- prep kernels ----------------
__global__ void tf32_copy(const float* __restrict__ in, float* __restrict__ out, long n) {
    long i = ((long)blockIdx.x * 256 + threadIdx.x) * 4;
    if (i >= n) return;
    float4 v = *(const float4*)(in + i);
    v.x = tfr(v.x); v.y = tfr(v.y); v.z = tfr(v.z); v.w = tfr(v.w);
    *(float4*)(out + i) = v;
}

__global__ void prep_wqkvb(const float* __restrict__ Wq, const float* __restrict__ Wk,
                           const float* __restrict__ Wv,
                           const float* __restrict__ bq, const float* __restrict__ bk,
                           const float* __restrict__ bv,
                           float* __restrict__ W, float* __restrict__ bias) {
    long idx = (long)blockIdx.x * 256 + threadIdx.x;
    if (idx >= (long)NLAYER * 3 * DMODEL * DMODEL) return;
    int l = (int)(idx / (3L * DMODEL * DMODEL));
    long rem = idx - (long)l * 3 * DMODEL * DMODEL;
    int r = (int)(rem >> 10), d = (int)(rem & 1023);
    int sel = r >> 10, rn = r & 1023;
    const float* src = sel == 0 ? Wq : (sel == 1 ? Wk : Wv);
    W[idx] = tfr(src[((long)l * DMODEL + rn) * DMODEL + d]);
    if (idx < NLAYER * 3 * DMODEL) {
        int lb = (int)(idx / (3 * DMODEL)), rb = (int)(idx % (3 * DMODEL));
        int selb = rb >> 10, rnb = rb & 1023;
        const float* b = selb == 0 ? bq : (selb == 1 ? bk : bv);
        bias[idx] = b[lb * DMODEL + rnb];
    }
}

__global__ void prep_wot(const float* __restrict__ Wo, const float* __restrict__ gate,
                         float* __restrict__ wot) {
    long idx = (long)blockIdx.x * 256 + threadIdx.x;
    if (idx >= (long)NLAYER * DMODEL * DMODEL) return;
    int l = (int)(idx >> 20);
    int d = (int)((idx >> 10) & 1023);
    int c = (int)(idx & 1023);
    int n = c >> 6, hh = c & 63;
    wot[idx] = tfr(Wo[((long)(l * NHEAD + n)) * (DMODEL * HDIM) + (long)d * HDIM + hh]
                   * gate[l * NHEAD + n]);
}

__global__ void prep_bos(const float* __restrict__ bo, const float* __restrict__ gate,
                         float* __restrict__ bos) {
    int idx = blockIdx.x * 256 + threadIdx.x;
    if (idx >= NLAYER * DMODEL) return;
    int l = idx >> 10, d = idx & 1023;
    float s = 0.f;
    for (int n = 0; n < NHEAD; n++)
        s += gate[l * NHEAD + n] * bo[(long)(l * NHEAD + n) * DMODEL + d];
    bos[idx] = s;
}

__global__ void embed_k(const int* __restrict__ ids, const float* __restrict__ wte,
                        const float* __restrict__ wpe, float* __restrict__ h) {
    long idx = (long)blockIdx.x * 256 + threadIdx.x;
    if (idx >= (long)BT * DMODEL) return;
    int bt = (int)(idx >> 10), d = (int)(idx & 1023);
    int t = bt & (TSEQ - 1);
    h[idx] = wte[(long)ids[bt] * DMODEL + d] + wpe[(long)t * DMODEL + d];
}

// ---------------- layernorm (layer-0 entry only) ----------------
__global__ void layernorm_k(const float* __restrict__ in, float* __restrict__ out,
                            const float* __restrict__ g, const float* __restrict__ b) {
    int row = blockIdx.x;
    const float* x = in + (long)row * DMODEL;
    float* y = out + (long)row * DMODEL;
    __shared__ float red[256];
    int tid = threadIdx.x;
    float s = 0.f;
    for (int i = tid; i < DMODEL; i += 256) s += x[i];
    red[tid] = s; __syncthreads();
    for (int o = 128; o > 0; o >>= 1) { if (tid < o) red[tid] += red[tid + o]; __syncthreads(); }
    float mean = red[0] * (1.0f / DMODEL);
    __syncthreads();
    float v = 0.f;
    for (int i = tid; i < DMODEL; i += 256) { float d = x[i] - mean; v += d * d; }
    red[tid] = v; __syncthreads();
    for (int o = 128; o > 0; o >>= 1) { if (tid < o) red[tid] += red[tid + o]; __syncthreads(); }
    float inv = rsqrtf(red[0] * (1.0f / DMODEL) + 1e-5f);
    for (int i = tid; i < DMODEL; i += 256)
        y[i] = tfr((x[i] - mean) * inv * g[i] + b[i]);
}

// ---------------- fused: h = (ADDH? h : 0) + p0 + p1 + bias;  x = LN(h) ------
template<bool ADDH>
__global__ void add_ln(const float* __restrict__ part, const float* __restrict__ bias,
                       float* __restrict__ h, float* __restrict__ x,
                       const float* __restrict__ g, const float* __restrict__ b) {
    int row = blockIdx.x;
    int tid = threadIdx.x;
    __shared__ float buf[DMODEL];
    __shared__ float red[256];
    const float* p0 = part + (long)row * DMODEL;
    const float* p1 = part + (long)BT * DMODEL + (long)row * DMODEL;
    float* hp = h + (long)row * DMODEL;
    float* xp = x + (long)row * DMODEL;
    float s = 0.f;
    for (int i = tid; i < DMODEL; i += 256) {
        float v = p0[i] + p1[i] + bias[i];
        if (ADDH) v += hp[i];
        buf[i] = v;
        hp[i] = v;
        s += v;
    }
    red[tid] = s; __syncthreads();
    for (int o = 128; o > 0; o >>= 1) { if (tid < o) red[tid] += red[tid + o]; __syncthreads(); }
    float mean = red[0] * (1.0f / DMODEL);
    __syncthreads();
    float v2 = 0.f;
    for (int i = tid; i < DMODEL; i += 256) { float d = buf[i] - mean; v2 += d * d; }
    red[tid] = v2; __syncthreads();
    for (int o = 128; o > 0; o >>= 1) { if (tid < o) red[tid] += red[tid + o]; __syncthreads(); }
    float inv = rsqrtf(red[0] * (1.0f / DMODEL) + 1e-5f);
    for (int i = tid; i < DMODEL; i += 256)
        xp[i] = tfr((buf[i] - mean) * inv * g[i] + b[i]);
}

__global__ void add2_k(const float* __restrict__ part, const float* __restrict__ bias,
                       float* __restrict__ out) {
    long i = ((long)blockIdx.x * 256 + threadIdx.x) * 4;
    if (i >= (long)BT * DMODEL) return;
    int n = (int)(i & (DMODEL - 1));
    float4 p0 = *(const float4*)(part + i);
    float4 p1 = *(const float4*)(part + (long)BT * DMODEL + i);
    float4 b4 = *(const float4*)(bias + n);
    float4 r4 = *(const float4*)(out + i);
    float4 v;
    v.x = p0.x + p1.x + b4.x + r4.x;
    v.y = p0.y + p1.y + b4.y + r4.y;
    v.z = p0.z + p1.z + b4.z + r4.z;
    v.w = p0.w + p1.w + b4.w + r4.w;
    *(float4*)(out + i) = v;
}

// ---------------- tf32 GEMM, 3-stage cp.async, 1 barrier/iter, ldmatrix -----
#define SMEM_STRIDE 36
#define TILE_U (128 * SMEM_STRIDE)
#define GEMM_SMEM_BYTES (6 * TILE_U * 4)   // 3 stages x (A+B) = 110592 B/CTA

// one 32-K chunk; fragments via ldmatrix.x4 (b16 view of tf32 data)
template<bool CVTA>
__device__ __forceinline__ void mma_chunk(
    uint32_t Abase, uint32_t Bbase,
    uint32_t offA0, uint32_t offA1,
    uint32_t offB0, uint32_t offB1, uint32_t offB2, uint32_t offB3,
    float acc[2][8][4]) {
    #pragma unroll
    for (int ks = 0; ks < 4; ks++) {
        uint32_t ko = (uint32_t)ks * 32;   // 8 floats along k
        uint32_t a[2][4];
        ldsm4(a[0][0], a[0][1], a[0][2], a[0][3], Abase + offA0 + ko);
        ldsm4(a[1][0], a[1][1], a[1][2], a[1][3], Abase + offA1 + ko);
        if (CVTA) {
            #pragma unroll
            for (int i = 0; i < 2; i++)
                #pragma unroll
                for (int q = 0; q < 4; q++)
                    a[i][q] = f2tf(__uint_as_float(a[i][q]));
        }
        uint32_t offB[4] = {offB0, offB1, offB2, offB3};
        #pragma unroll
        for (int jj = 0; jj < 4; jj++) {
            uint32_t b0, b1, b2, b3;
            ldsm4(b0, b1, b2, b3, Bbase + offB[jj] + ko);
            mma_tf32(acc[0][2 * jj],     a[0][0], a[0][1], a[0][2], a[0][3], b0, b1);
            mma_tf32(acc[1][2 * jj],     a[1][0], a[1][1], a[1][2], a[1][3], b0, b1);
            mma_tf32(acc[0][2 * jj + 1], a[0][0], a[0][1], a[0][2], a[0][3], b2, b3);
            mma_tf32(acc[1][2 * jj + 1], a[1][0], a[1][1], a[1][2], a[1][3], b2, b3);
        }
    }
}

template<int EPI, bool BIAS, bool RES, bool CVTA, bool ROUND>
__global__ __launch_bounds__(256, 2) void gemm_cp(
    const float* __restrict__ A, const float* __restrict__ Bm,
    const float* __restrict__ bias, const float* __restrict__ res,
    float* __restrict__ C, int M, int N, int K, int lda, int ldb, int ldc) {
    extern __shared__ float sm[];
    float* As = sm;                    // [3][TILE_U]
    float* Bs = sm + 3 * TILE_U;       // [3][TILE_U]
    const uint32_t AsU = s2u(As), BsU = s2u(Bs);

    int tid = threadIdx.x, lane = tid & 31, warp = tid >> 5;
    int wm = warp & 3, wn = warp >> 2;
    int m0 = blockIdx.y * 128, n0 = blockIdx.x * 128;
    const float* Ag = A + (long)m0 * lda;
    const float* Bg = Bm + (long)n0 * ldb;

    const float* Asrc[4]; const float* Bsrc[4];
    uint32_t Adst[4], Bdst[4];
    #pragma unroll
    for (int i = 0; i < 4; i++) {
        int idx = tid + i * 256;
        int r = idx >> 3, c = (idx & 7) * 4;
        Asrc[i] = Ag + (long)r * lda + c;
        Bsrc[i] = Bg + (long)r * ldb + c;
        Adst[i] = AsU + (uint32_t)(r * SMEM_STRIDE + c) * 4;
        Bdst[i] = BsU + (uint32_t)(r * SMEM_STRIDE + c) * 4;
    }

    float acc[2][8][4];
    #pragma unroll
    for (int i = 0; i < 2; i++)
        #pragma unroll
        for (int j = 0; j < 8; j++)
            #pragma unroll
            for (int q = 0; q < 4; q++) acc[i][j][q] = 0.f;

    int mat = lane >> 3, r8 = lane & 7;
    uint32_t offA0 = (uint32_t)(((wm * 32 + (mat & 1) * 8 + r8) * SMEM_STRIDE
                                 + (mat >> 1) * 4) * 4);
    uint32_t offA1 = offA0 + (uint32_t)(16 * SMEM_STRIDE * 4);
    uint32_t offB[4];
    #pragma unroll
    for (int jj = 0; jj < 4; jj++)
        offB[jj] = (uint32_t)(((wn * 64 + jj * 16 + (mat >> 1) * 8 + r8) * SMEM_STRIDE
                               + (mat & 1) * 4) * 4);

    const int NC = K >> 5;
    // prologue: stages 0,1
    #pragma unroll
    for (int s = 0; s < 2; s++) {
        if (s < NC) {
            uint32_t so = (uint32_t)(s * TILE_U) * 4;
            #pragma unroll
            for (int i = 0; i < 4; i++) {
                CP_ASYNC16(Adst[i] + so, Asrc[i] + s * 32);
                CP_ASYNC16(Bdst[i] + so, Bsrc[i] + s * 32);
            }
            CP_COMMIT();
        }
    }

    int sw = 2 % 3;   // write stage for chunk c+2
    int sr = 0;       // read stage for chunk c
    for (int c = 0; c < NC; c++) {
        if (c + 1 < NC) { CP_WAIT1(); } else { CP_WAIT0(); }
        __syncthreads();
        if (c + 2 < NC) {
            uint32_t so = (uint32_t)(sw * TILE_U) * 4;
            int kc = (c + 2) * 32;
            #pragma unroll
            for (int i = 0; i < 4; i++) {
                CP_ASYNC16(Adst[i] + so, Asrc[i] + kc);
                CP_ASYNC16(Bdst[i] + so, Bsrc[i] + kc);
            }
            CP_COMMIT();
        }
        uint32_t ro = (uint32_t)(sr * TILE_U) * 4;
        mma_chunk<CVTA>(AsU + ro, BsU + ro, offA0, offA1,
                        offB[0], offB[1], offB[2], offB[3], acc);
        sw = sw + 1 == 3 ? 0 : sw + 1;
        sr = sr + 1 == 3 ? 0 : sr + 1;
    }

    #pragma unroll
    for (int i = 0; i < 2; i++) {
        int m = m0 + wm * 32 + i * 16 + (lane >> 2);
        #pragma unroll
        for (int j = 0; j < 8; j++) {
            int n = n0 + wn * 64 + j * 8 + (lane & 3) * 2;
            #pragma unroll
            for (int q = 0; q < 2; q++) {
                int mm = m + q * 8;
                float v0 = acc[i][j][q * 2 + 0];
                float v1 = acc[i][j][q * 2 + 1];
                if (BIAS) { v0 += bias[n]; v1 += bias[n + 1]; }
                if (RES)  { v0 += res[(long)mm * ldc + n]; v1 += res[(long)mm * ldc + n + 1]; }
                if (EPI == 2) {
                    v0 = 0.5f * v0 * (1.0f + erff(v0 * 0.70710678118654752f));
                    v1 = 0.5f * v1 * (1.0f + erff(v1 * 0.70710678118654752f));
                }
                if (ROUND) { v0 = tfr(v0); v1 = tfr(v1); }
                C[(long)mm * ldc + n]     = v0;
                C[(long)mm * ldc + n + 1] = v1;
            }
        }
    }
}

// ---------------- split-K / dual-source tf32 GEMM (3-stage, ldmatrix) -------
template<bool CVTA>
__global__ __launch_bounds__(256, 2) void gemm_sk(
    const float* __restrict__ A0, const float* __restrict__ A1,
    const float* __restrict__ Bm, float* __restrict__ part,
    int K2, int lda, int ldb, int boff) {
    extern __shared__ float sm[];
    float* As = sm;
    float* Bs = sm + 3 * TILE_U;
    const uint32_t AsU = s2u(As), BsU = s2u(Bs);

    int tid = threadIdx.x, lane = tid & 31, warp = tid >> 5;
    int wm = warp & 3, wn = warp >> 2;
    int m0 = blockIdx.y * 128, n0 = blockIdx.x * 128;
    int z = blockIdx.z;
    const float* Ag = (z ? A1 : A0) + (long)m0 * lda;
    const float* Bg = Bm + (long)n0 * ldb + (long)z * boff;
    float* C = part + (long)z * BT * DMODEL;

    const float* Asrc[4]; const float* Bsrc[4];
    uint32_t Adst[4], Bdst[4];
    #pragma unroll
    for (int i = 0; i < 4; i++) {
        int idx = tid + i * 256;
        int r = idx >> 3, c = (idx & 7) * 4;
        Asrc[i] = Ag + (long)r * lda + c;
        Bsrc[i] = Bg + (long)r * ldb + c;
        Adst[i] = AsU + (uint32_t)(r * SMEM_STRIDE + c) * 4;
        Bdst[i] = BsU + (uint32_t)(r * SMEM_STRIDE + c) * 4;
    }

    float acc[2][8][4];
    #pragma unroll
    for (int i = 0; i < 2; i++)
        #pragma unroll
        for (int j = 0; j < 8; j++)
            #pragma unroll
            for (int q = 0; q < 4; q++) acc[i][j][q] = 0.f;

    int mat = lane >> 3, r8 = lane & 7;
    uint32_t offA0 = (uint32_t)(((wm * 32 + (mat & 1) * 8 + r8) * SMEM_STRIDE
                                 + (mat >> 1) * 4) * 4);
    uint32_t offA1 = offA0 + (uint32_t)(16 * SMEM_STRIDE * 4);
    uint32_t offB[4];
    #pragma unroll
    for (int jj = 0; jj < 4; jj++)
        offB[jj] = (uint32_t)(((wn * 64 + jj * 16 + (mat >> 1) * 8 + r8) * SMEM_STRIDE
                               + (mat & 1) * 4) * 4);

    const int NC = K2 >> 5;
    #pragma unroll
    for (int s = 0; s < 2; s++) {
        if (s < NC) {
            uint32_t so = (uint32_t)(s * TILE_U) * 4;
            #pragma unroll
            for (int i = 0; i < 4; i++) {
                CP_ASYNC16(Adst[i] + so, Asrc[i] + s * 32);
                CP_ASYNC16(Bdst[i] + so, Bsrc[i] + s * 32);
            }
            CP_COMMIT();
        }
    }

    int sw = 2 % 3;
    int sr = 0;
    for (int c = 0; c < NC; c++) {
        if (c + 1 < NC) { CP_WAIT1(); } else { CP_WAIT0(); }
        __syncthreads();
        if (c + 2 < NC) {
            uint32_t so = (uint32_t)(sw * TILE_U) * 4;
            int kc = (c + 2) * 32;
            #pragma unroll
            for (int i = 0; i < 4; i++) {
                CP_ASYNC16(Adst[i] + so, Asrc[i] + kc);
                CP_ASYNC16(Bdst[i] + so, Bsrc[i] + kc);
            }
            CP_COMMIT();
        }
        uint32_t ro = (uint32_t)(sr * TILE_U) * 4;
        mma_chunk<CVTA>(AsU + ro, BsU + ro, offA0, offA1,
                        offB[0], offB[1], offB[2], offB[3], acc);
        sw = sw + 1 == 3 ? 0 : sw + 1;
        sr = sr + 1 == 3 ? 0 : sr + 1;
    }

    #pragma unroll
    for (int i = 0; i < 2; i++) {
        int m = m0 + wm * 32 + i * 16 + (lane >> 2);
        #pragma unroll
        for (int j = 0; j < 8; j++) {
            int n = n0 + wn * 64 + j * 8 + (lane & 3) * 2;
            #pragma unroll
            for (int q = 0; q < 2; q++) {
                int mm = m + q * 8;
                C[(long)mm * DMODEL + n]     = acc[i][j][q * 2 + 0];
                C[(long)mm * DMODEL + n + 1] = acc[i][j][q * 2 + 1];
            }
        }
    }
}

// ---------------- attention scores: bf16 3-pass mma ----------------
#define SC_STR 36
#define SC_PLANE (128 * SC_STR)
#define SC_SMEM (4 * SC_PLANE * 4)

__global__ __launch_bounds__(256) void attn_scores_tc(
    const float* __restrict__ qkv, float* __restrict__ S) {
    int bh = blockIdx.z;
    int b = bh >> 4, n = bh & 15;
    int s0 = blockIdx.x * 128, t0 = blockIdx.y * 128;
    if (s0 > t0) return;
    extern __shared__ uint32_t smq[];
    uint32_t* Qh = smq;
    uint32_t* Ql = smq + SC_PLANE;
    uint32_t* Kh = smq + 2 * SC_PLANE;
    uint32_t* Kl = smq + 3 * SC_PLANE;
    int tid = threadIdx.x, lane = tid & 31, warp = tid >> 5;
    const float* Qp = qkv + ((long)(b * TSEQ + t0)) * (3 * DMODEL) + n * HDIM;
    const float* Kp = qkv + ((long)(b * TSEQ + s0)) * (3 * DMODEL) + DMODEL + n * HDIM;
    for (int g = tid; g < 2048; g += 256) {
        int isK = g >= 1024;
        int gg = g & 1023;
        int r = gg >> 3, c8 = (gg & 7) * 8;
        const float* src = (isK ? Kp : Qp) + (long)r * (3 * DMODEL) + c8;
        float4 v0 = *(const float4*)src;
        float4 v1 = *(const float4*)(src + 4);
        uint4 hi, lo;
        split8(v0, v1, hi, lo);
        int off = r * SC_STR + c8 / 2;
        *(uint4*)((isK ? Kh : Qh) + off) = hi;
        *(uint4*)((isK ? Kl : Ql) + off) = lo;
    }
    __syncthreads();

    int wm = warp & 3, wn = warp >> 2;
    int mrow = wm * 32 + (lane >> 2);
    int nrow = wn * 64 + (lane >> 2);
    int kt = lane & 3;
    float acc[2][8][4];
    #pragma unroll
    for (int i = 0; i < 2; i++)
        #pragma unroll
        for (int j = 0; j < 8; j++)
            #pragma unroll
            for (int q = 0; q < 4; q++) acc[i][j][q] = 0.f;

    const uint32_t* Ap[3] = {Qh, Qh, Ql};
    const uint32_t* Bp[3] = {Kh, Kl, Kh};
    #pragma unroll
    for (int p = 0; p < 3; p++) {
        #pragma unroll
        for (int ks = 0; ks < 4; ks++) {
            int kk = ks * 8 + kt;
            unsigned af[2][4];
            #pragma unroll
            for (int i = 0; i < 2; i++) {
                const uint32_t* base = Ap[p] + (mrow + i * 16) * SC_STR;
                af[i][0] = base[kk];
                af[i][1] = base[8 * SC_STR + kk];
                af[i][2] = base[kk + 4];
                af[i][3] = base[8 * SC_STR + kk + 4];
            }
            #pragma unroll
            for (int j = 0; j < 8; j++) {
                const uint32_t* bb = Bp[p] + (nrow + j * 8) * SC_STR;
                unsigned b0 = bb[kk], b1 = bb[kk + 4];
                #pragma unroll
                for (int i = 0; i < 2; i++)
                    mma_bf16x(acc[i][j], af[i][0], af[i][1], af[i][2], af[i][3], b0, b1);
            }
        }
    }
    float* Sp = S + ((long)bh * TSEQ + t0) * TSEQ + s0;
    #pragma unroll
    for (int i = 0; i < 2; i++) {
        int rr = wm * 32 + i * 16 + (lane >> 2);
        #pragma unroll
        for (int j = 0; j < 8; j++) {
            int cc = wn * 64 + j * 8 + (lane & 3) * 2;
            #pragma unroll
            for (int q = 0; q < 2; q++) {
                Sp[(long)(rr + q * 8) * TSEQ + cc]     = acc[i][j][q * 2 + 0] * 0.125f;
                Sp[(long)(rr + q * 8) * TSEQ + cc + 1] = acc[i][j][q * 2 + 1] * 0.125f;
            }
        }
    }
}

// ---------------- softmax ----------------
__global__ void softmax_rows(float* __restrict__ S) {
    int t = blockIdx.x, bh = blockIdx.y;
    float* row = S + ((long)bh * TSEQ + t) * TSEQ;
    int len = t + 1;
    __shared__ float red[128];
    int tid = threadIdx.x;
    float mx = -1e30f;
    for (int s = tid; s < len; s += 128) mx = fmaxf(mx, row[s]);
    red[tid] = mx; __syncthreads();
    for (int o = 64; o > 0; o >>= 1) { if (tid < o) red[tid] = fmaxf(red[tid], red[tid + o]); __syncthreads(); }
    mx = red[0]; __syncthreads();
    float sum = 0.f;
    for (int s = tid; s < len; s += 128) { float e = __expf(row[s] - mx); row[s] = e; sum += e; }
    red[tid] = sum; __syncthreads();
    for (int o = 64; o > 0; o >>= 1) { if (tid < o) red[tid] += red[tid + o]; __syncthreads(); }
    float inv = 1.0f / red[0];
    for (int s = tid; s < len; s += 128) row[s] *= inv;
    for (int s = len + tid; s < TSEQ; s += 128) row[s] = 0.0f;
}

// ---------------- V transpose ----------------
__global__ void transpose_v(const float* __restrict__ qkv, float* __restrict__ Vt) {
    int bh = blockIdx.z;
    int b = bh >> 4, n = bh & 15;
    int tt = blockIdx.x * 32, dd = blockIdx.y * 32;
    __shared__ float tile[32][33];
    int tx = threadIdx.x, ty = threadIdx.y;
    #pragma unroll
    for (int i = 0; i < 4; i++) {
        int t = tt + ty + i * 8;
        tile[ty + i * 8][tx] =
            qkv[((long)(b * TSEQ + t)) * (3 * DMODEL) + 2 * DMODEL + n * HDIM + dd + tx];
    }
    __syncthreads();
    #pragma unroll
    for (int i = 0; i < 4; i++) {
        int d = dd + ty + i * 8;
        Vt[((long)bh * HDIM + d) * TSEQ + tt + tx] = tile[tx][ty + i * 8];
    }
}

// ---------------- attention PV: bf16 3-pass mma (tf32-rounded output) -------
#define PV_STR 20

__global__ __launch_bounds__(256) void attn_pv_tc(
    const float* __restrict__ P, const float* __restrict__ Vt, float* __restrict__ O) {
    int bh = blockIdx.y;
    int b = bh >> 4, n = bh & 15;
    int t0 = blockIdx.x * 128;
    __shared__ uint32_t Ph[128 * PV_STR], Pl[128 * PV_STR];
    __shared__ uint32_t Vh[64 * PV_STR],  Vl[64 * PV_STR];
    int tid = threadIdx.x, lane = tid & 31, warp = tid >> 5;
    int wm = warp & 3, wn = warp >> 2;
    int mrow = wm * 32 + (lane >> 2);
    int nrow = wn * 32 + (lane >> 2);
    int kt = lane & 3;
    const float* Pp = P + ((long)bh * TSEQ + t0) * TSEQ;
    const float* Vp = Vt + (long)bh * HDIM * TSEQ;

    float acc[2][4][4];
    #pragma unroll
    for (int i = 0; i < 2; i++)
        #pragma unroll
        for (int j = 0; j < 4; j++)
            #pragma unroll
            for (int q = 0; q < 4; q++) acc[i][j][q] = 0.f;

    int kmax = t0 + 128;
    for (int k0 = 0; k0 < kmax; k0 += 32) {
        for (int g = tid; g < 768; g += 256) {
            const float* src; uint32_t *dh, *dl;
            if (g < 512) {
                int r = g >> 2, c8 = (g & 3) * 8;
                src = Pp + (long)r * TSEQ + k0 + c8;
                dh = Ph + r * PV_STR + c8 / 2; dl = Pl + r * PV_STR + c8 / 2;
            } else {
                int v = g - 512;
                int r = v >> 2, c8 = (v & 3) * 8;
                src = Vp + (long)r * TSEQ + k0 + c8;
                dh = Vh + r * PV_STR + c8 / 2; dl = Vl + r * PV_STR + c8 / 2;
            }
            float4 v0 = *(const float4*)src;
            float4 v1 = *(const float4*)(src + 4);
            uint4 hi, lo;
            split8(v0, v1, hi, lo);
            *(uint4*)dh = hi;
            *(uint4*)dl = lo;
        }
        __syncthreads();
        const uint32_t* Ap[3] = {Ph, Ph, Pl};
        const uint32_t* Bp[3] = {Vh, Vl, Vh};
        #pragma unroll
        for (int p = 0; p < 3; p++) {
            #pragma unroll
            for (int ks = 0; ks < 2; ks++) {
                int kk = ks * 8 + kt;
                unsigned af[2][4];
                #pragma unroll
                for (int i = 0; i < 2; i++) {
                    const uint32_t* base = Ap[p] + (mrow + i * 16) * PV_STR;
                    af[i][0] = base[kk];
                    af[i][1] = base[8 * PV_STR + kk];
                    af[i][2] = base[kk + 4];
                    af[i][3] = base[8 * PV_STR + kk + 4];
                }
                #pragma unroll
                for (int j = 0; j < 4; j++) {
                    const uint32_t* bb = Bp[p] + (nrow + j * 8) * PV_STR;
                    unsigned b0 = bb[kk], b1 = bb[kk + 4];
                    #pragma unroll
                    for (int i = 0; i < 2; i++)
                        mma_bf16x(acc[i][j], af[i][0], af[i][1], af[i][2], af[i][3], b0, b1);
                }
            }
        }
        __syncthreads();
    }
    #pragma unroll
    for (int i = 0; i < 2; i++) {
        int rr = t0 + wm * 32 + i * 16 + (lane >> 2);
        #pragma unroll
        for (int j = 0; j < 4; j++) {
            int cc = n * HDIM + wn * 32 + j * 8 + (lane & 3) * 2;
            #pragma unroll
            for (int q = 0; q < 2; q++) {
                O[(long)(b * TSEQ + rr + q * 8) * DMODEL + cc]     = tfr(acc[i][j][q * 2 + 0]);
                O[(long)(b * TSEQ + rr + q * 8) * DMODEL + cc + 1] = tfr(acc[i][j][q * 2 + 1]);
            }
        }
    }
}

// ---------------- orchestration ----------------
extern "C" void kernel_launch(void* const* d_in, const int* in_sizes, int n_in,
                              void* d_out, int out_size) {
    const int*   ids  = (const int*)d_in[0];
    const float* wte  = (const float*)d_in[1];
    const float* wpe  = (const float*)d_in[2];
    const float* Wq   = (const float*)d_in[3];
    const float* bq   = (const float*)d_in[4];
    const float* Wk   = (const float*)d_in[5];
    const float* bk   = (const float*)d_in[6];
    const float* Wv   = (const float*)d_in[7];
    const float* bv   = (const float*)d_in[8];
    const float* Wo   = (const float*)d_in[9];
    const float* bo   = (const float*)d_in[10];
    const float* gate = (const float*)d_in[11];
    const float* ln1g = (const float*)d_in[12];
    const float* ln1b = (const float*)d_in[13];
    const float* ln2g = (const float*)d_in[14];
    const float* ln2b = (const float*)d_in[15];
    const float* w1   = (const float*)d_in[16];
    const float* b1   = (const float*)d_in[17];
    const float* w2   = (const float*)d_in[18];
    const float* b2   = (const float*)d_in[19];
    const float* skw  = (const float*)d_in[20];
    const float* skb  = (const float*)d_in[21];
    const float* lnfg = (const float*)d_in[22];
    const float* lnfb = (const float*)d_in[23];
    float* out = (float*)d_out;

    float *h, *x, *o, *part, *ff, *qkv, *vt, *sc, *enc, *wot, *bos, *wqkv, *bqkv;
    float *w1c, *w2c, *skwc, *wtec;
    cudaGetSymbolAddress((void**)&h,    g_h);
    cudaGetSymbolAddress((void**)&x,    g_x);
    cudaGetSymbolAddress((void**)&o,    g_o);
    cudaGetSymbolAddress((void**)&part, g_part);
    cudaGetSymbolAddress((void**)&ff,   g_ff);
    cudaGetSymbolAddress((void**)&qkv,  g_qkv);
    cudaGetSymbolAddress((void**)&vt,   g_vt);
    cudaGetSymbolAddress((void**)&sc,   g_sc);
    cudaGetSymbolAddress((void**)&enc,  g_enc);
    cudaGetSymbolAddress((void**)&wot,  g_wot);
    cudaGetSymbolAddress((void**)&bos,  g_bos);
    cudaGetSymbolAddress((void**)&wqkv, g_wqkv);
    cudaGetSymbolAddress((void**)&bqkv, g_bqkv);
    cudaGetSymbolAddress((void**)&w1c,  g_w1c);
    cudaGetSymbolAddress((void**)&w2c,  g_w2c);
    cudaGetSymbolAddress((void**)&skwc, g_skwc);
    cudaGetSymbolAddress((void**)&wtec, g_wtec);

    cudaFuncSetAttribute(gemm_cp<0, true,  false, false, false>, cudaFuncAttributeMaxDynamicSharedMemorySize, GEMM_SMEM_BYTES);
    cudaFuncSetAttribute(gemm_cp<2, true,  false, false, true >, cudaFuncAttributeMaxDynamicSharedMemorySize, GEMM_SMEM_BYTES);
    cudaFuncSetAttribute(gemm_cp<0, false, false, false, false>, cudaFuncAttributeMaxDynamicSharedMemorySize, GEMM_SMEM_BYTES);
    cudaFuncSetAttribute(gemm_sk<false>, cudaFuncAttributeMaxDynamicSharedMemorySize, GEMM_SMEM_BYTES);
    cudaFuncSetAttribute(gemm_sk<true >, cudaFuncAttributeMaxDynamicSharedMemorySize, GEMM_SMEM_BYTES);
    cudaFuncSetAttribute(attn_scores_tc, cudaFuncAttributeMaxDynamicSharedMemorySize, SC_SMEM);

    dim3 gQKV(3 * DMODEL / 128, BT / 128);
    dim3 gSK(DMODEL / 128, BT / 128, 2);
    dim3 gF(FINNER / 128, BT / 128);
    dim3 gV(VOCAB / 128, BT / 128);
    int nAdd = (BT * DMODEL / 4 + 255) / 256;

    // keep gemm_cp (QKV, layer 0) as launch #4 for ncu visibility
    prep_wqkvb<<<(int)(((long)NLAYER * 3 * DMODEL * DMODEL + 255) / 256), 256>>>(
        Wq, Wk, Wv, bq, bk, bv, wqkv, bqkv);
    embed_k<<<(BT * DMODEL + 255) / 256, 256>>>(ids, wte, wpe, h);
    layernorm_k<<<BT, 256>>>(h, x, ln1g, ln1b);

    for (int i = 0; i < NLAYER; i++) {
        gemm_cp<0, true, false, false, false><<<gQKV, 256, GEMM_SMEM_BYTES>>>(
            x, wqkv + (long)i * 3 * DMODEL * DMODEL, bqkv + i * 3 * DMODEL, nullptr, qkv,
            BT, 3 * DMODEL, DMODEL, DMODEL, DMODEL, 3 * DMODEL);

        attn_scores_tc<<<dim3(TSEQ / 128, TSEQ / 128, BBATCH * NHEAD), 256, SC_SMEM>>>(qkv, sc);
        softmax_rows<<<dim3(TSEQ, BBATCH * NHEAD), 128>>>(sc);
        transpose_v<<<dim3(TSEQ / 32, HDIM / 32, BBATCH * NHEAD), dim3(32, 8)>>>(qkv, vt);
        attn_pv_tc<<<dim3(TSEQ / 128, BBATCH * NHEAD), 256>>>(sc, vt, o);

        if (i == 0) {
            prep_wot<<<(NLAYER * DMODEL * DMODEL + 255) / 256, 256>>>(Wo, gate, wot);
            prep_bos<<<(NLAYER * DMODEL + 255) / 256, 256>>>(bo, gate, bos);
            long n1 = (long)NLAYER * FINNER * DMODEL;
            tf32_copy<<<(int)((n1 / 4 + 255) / 256), 256>>>(w1, w1c, n1);
            tf32_copy<<<(int)((n1 / 4 + 255) / 256), 256>>>(w2, w2c, n1);
            long n2 = (long)NLAYER * DMODEL * 2 * DMODEL;
            tf32_copy<<<(int)((n2 / 4 + 255) / 256), 256>>>(skw, skwc, n2);
            long n3 = (long)VOCAB * DMODEL;
            tf32_copy<<<(int)((n3 / 4 + 255) / 256), 256>>>(wte, wtec, n3);
        }

        gemm_sk<false><<<gSK, 256, GEMM_SMEM_BYTES>>>(
            o, o + 512, wot + (long)i * DMODEL * DMODEL, part,
            512, DMODEL, DMODEL, 512);
        add_ln<true><<<BT, 256>>>(part, bos + i * DMODEL, h, x,
                                  ln2g + i * DMODEL, ln2b + i * DMODEL);
        if (i < NLAYER / 2)
            tf32_copy<<<nAdd, 256>>>(h, enc + (long)i * BT * DMODEL, (long)BT * DMODEL);

        gemm_cp<2, true, false, false, true><<<gF, 256, GEMM_SMEM_BYTES>>>(
            x, w1c + (long)i * FINNER * DMODEL, b1 + i * FINNER, nullptr, ff,
            BT, FINNER, DMODEL, DMODEL, DMODEL, FINNER);
        gemm_sk<false><<<gSK, 256, GEMM_SMEM_BYTES>>>(
            ff, ff + 2048, w2c + (long)i * DMODEL * FINNER, part,
            2048, FINNER, FINNER, 2048);

        if (i < NLAYER / 2) {
            add_ln<true><<<BT, 256>>>(part, b2 + i * DMODEL, h, x,
                                      ln1g + (i + 1) * DMODEL, ln1b + (i + 1) * DMODEL);
        } else {
            add2_k<<<nAdd, 256>>>(part, b2 + i * DMODEL, h);
            int el = NLAYER - i - 1;
            const float* sw = skwc + (long)i * DMODEL * 2 * DMODEL;
            gemm_sk<true><<<gSK, 256, GEMM_SMEM_BYTES>>>(
                h, enc + (long)el * BT * DMODEL, sw, part,
                DMODEL, DMODEL, 2 * DMODEL, DMODEL);
            if (i + 1 < NLAYER) {
                add_ln<false><<<BT, 256>>>(part, skb + i * DMODEL, h, x,
                                           ln1g + (i + 1) * DMODEL, ln1b + (i + 1) * DMODEL);
            } else {
                add_ln<false><<<BT, 256>>>(part, skb + i * DMODEL, h, x, lnfg, lnfb);
            }
        }
    }

    gemm_cp<0, false, false, false, false><<<gV, 256, GEMM_SMEM_BYTES>>>(
        x, wtec, nullptr, nullptr, out, BT, VOCAB, DMODEL, DMODEL, DMODEL, VOCAB);
}